// round 11
// baseline (speedup 1.0000x reference)
#include <cuda_runtime.h>
#include <cuda_bf16.h>
#include <math.h>
#include <stdint.h>

#define DHID 1024
#define MAXN 10240
#define MAXE 163840
#define NEG_SLOPE 0.1f
#define EPS_V 1e-5f

// ---------------- device scratch ----------------
__device__ float g_h[(size_t)MAXN * DHID];   // h = x @ W
__device__ __nv_bfloat16 g_x_hi[(size_t)MAXN * DHID];
__device__ __nv_bfloat16 g_x_lo[(size_t)MAXN * DHID];
__device__ __nv_bfloat16 g_w_hi[DHID * DHID];
__device__ __nv_bfloat16 g_w_lo[DHID * DHID];
__device__ float g_al[MAXN];
__device__ float g_ar[MAXN];
__device__ int   g_counts[MAXN];
__device__ int   g_cursor[MAXN];
__device__ int   g_offsets[MAXN + 1];
__device__ int   g_src[MAXE];
__device__ int   g_dst[MAXE];
__device__ int   g_dst_sorted[MAXE];
__device__ float g_e_sorted[MAXE];
__device__ int   g_is64;

__device__ __forceinline__ uint32_t smem_u32(const void* p) {
    uint32_t a;
    asm("{ .reg .u64 t; cvta.to.shared.u64 t, %1; cvt.u32.u64 %0, t; }" : "=r"(a) : "l"(p));
    return a;
}

__device__ __forceinline__ uint2 split_hi(float4 v, float4* rem) {
    __nv_bfloat16 h0 = __float2bfloat16(v.x);
    __nv_bfloat16 h1 = __float2bfloat16(v.y);
    __nv_bfloat16 h2 = __float2bfloat16(v.z);
    __nv_bfloat16 h3 = __float2bfloat16(v.w);
    rem->x = v.x - __bfloat162float(h0);
    rem->y = v.y - __bfloat162float(h1);
    rem->z = v.z - __bfloat162float(h2);
    rem->w = v.w - __bfloat162float(h3);
    uint2 u;
    u.x = (uint32_t)__bfloat16_as_ushort(h0) | ((uint32_t)__bfloat16_as_ushort(h1) << 16);
    u.y = (uint32_t)__bfloat16_as_ushort(h2) | ((uint32_t)__bfloat16_as_ushort(h3) << 16);
    return u;
}
__device__ __forceinline__ uint2 pack_bf16(float4 v) {
    uint2 u;
    u.x = (uint32_t)__bfloat16_as_ushort(__float2bfloat16(v.x)) |
          ((uint32_t)__bfloat16_as_ushort(__float2bfloat16(v.y)) << 16);
    u.y = (uint32_t)__bfloat16_as_ushort(__float2bfloat16(v.z)) |
          ((uint32_t)__bfloat16_as_ushort(__float2bfloat16(v.w)) << 16);
    return u;
}

// ---------------- init ----------------
__global__ void init_kernel(int N) {
    int i = blockIdx.x * blockDim.x + threadIdx.x;
    if (i < N) { g_counts[i] = 0; g_cursor[i] = 0; g_al[i] = 0.f; g_ar[i] = 0.f; }
    if (i == 0) g_is64 = 1;
}

__global__ void detect_kernel(const void* __restrict__ src, int E, int N) {
    int n = E / 2; if (n > 4096) n = 4096;
    for (int k = threadIdx.x; k < n; k += blockDim.x) {
        long long v = ((const long long*)src)[k];
        if (v < 0 || v >= (long long)N) g_is64 = 0;
    }
}

// convert + fused src histogram
__global__ void convert_kernel(const void* __restrict__ src,
                               const void* __restrict__ dst, int E) {
    int k = blockIdx.x * blockDim.x + threadIdx.x;
    if (k >= E) return;
    int s, d;
    if (g_is64) {
        s = (int)((const long long*)src)[k];
        d = (int)((const long long*)dst)[k];
    } else {
        s = ((const int*)src)[k];
        d = ((const int*)dst)[k];
    }
    g_src[k] = s;
    g_dst[k] = d;
    atomicAdd(&g_counts[s], 1);
}

// ---------------- prepass: fp32 -> bf16 hi/lo split ----------------
__global__ void split_kernel(const float4* __restrict__ in,
                             uint2* __restrict__ hi, uint2* __restrict__ lo, int n4) {
    int i = blockIdx.x * blockDim.x + threadIdx.x;
    if (i >= n4) return;
    float4 v = in[i];
    float4 rem;
    uint2 uh = split_hi(v, &rem);
    uint2 ul = pack_bf16(rem);
    hi[i] = uh;
    lo[i] = ul;
}

// ================== tensor-core GEMM via mma.sync (HMMA) ==================
// h = x @ W, split-bf16 (hi*hi + hi*lo + lo*hi), fp32 accum.
// CTA tile 128x64, BK=64, 2-stage cp.async pipeline, 2 CTAs/SM.
// 8 warps, each 32x32 (2x4 m16n8k16 tiles). Fused al/ar epilogue.
#define BM 128
#define BN 64
#define BK 64
#define LDA 72    // row stride (bf16) = 144B: conflict-free + 16B aligned
#define LDB 72

#define OFF_AH 0
#define OFF_AL (BM * LDA * 2)                 // 18432
#define OFF_BH (OFF_AL + BM * LDA * 2)        // 36864
#define OFF_BL (OFF_BH + BK * LDB * 2)        // 46080
#define STG    (OFF_BL + BK * LDB * 2)        // 55296 bytes / stage
#define STAGES 2
#define GEMM_SMEM (STAGES * STG)              // 110592 (x2 CTA = 221K < 228K)

__device__ __forceinline__ void mma16816(float* c, const uint32_t* a, const uint32_t* b) {
    asm volatile(
        "mma.sync.aligned.m16n8k16.row.col.f32.bf16.bf16.f32 "
        "{%0,%1,%2,%3}, {%4,%5,%6,%7}, {%8,%9}, {%0,%1,%2,%3};"
        : "+f"(c[0]), "+f"(c[1]), "+f"(c[2]), "+f"(c[3])
        : "r"(a[0]), "r"(a[1]), "r"(a[2]), "r"(a[3]), "r"(b[0]), "r"(b[1]));
}
__device__ __forceinline__ void ldsm4(uint32_t* r, uint32_t addr) {
    asm volatile("ldmatrix.sync.aligned.m8n8.x4.shared.b16 {%0,%1,%2,%3}, [%4];"
                 : "=r"(r[0]), "=r"(r[1]), "=r"(r[2]), "=r"(r[3]) : "r"(addr));
}
__device__ __forceinline__ void ldsm4t(uint32_t* r, uint32_t addr) {
    asm volatile("ldmatrix.sync.aligned.m8n8.x4.trans.shared.b16 {%0,%1,%2,%3}, [%4];"
                 : "=r"(r[0]), "=r"(r[1]), "=r"(r[2]), "=r"(r[3]) : "r"(addr));
}
__device__ __forceinline__ void cpa16(uint32_t s, const void* g, int sz) {
    asm volatile("cp.async.cg.shared.global [%0], [%1], 16, %2;"
                 :: "r"(s), "l"(g), "r"(sz) : "memory");
}
#define CP_COMMIT() asm volatile("cp.async.commit_group;" ::: "memory")
#define CP_WAIT1()  asm volatile("cp.async.wait_group 1;" ::: "memory")

__global__ __launch_bounds__(256, 2)
void gemm_mma_kernel(const float* __restrict__ avec, int M) {
    extern __shared__ __align__(16) char sm[];
    uint32_t sbase = smem_u32(sm);

    const int tid = threadIdx.x;
    const int lane = tid & 31;
    const int wid = tid >> 5;
    const int wm = wid & 3;          // 0..3 -> 32-row slab
    const int wn = wid >> 2;         // 0..1 -> 32-col slab
    const int m0 = blockIdx.y * BM;
    const int n0 = blockIdx.x * BN;

    const int lr = (lane & 7) + ((lane >> 3) & 1) * 8;
    const int lc8 = ((lane >> 4) & 1) * 8;

    float C[2][4][4];
#pragma unroll
    for (int i = 0; i < 2; i++)
#pragma unroll
        for (int j = 0; j < 4; j++)
#pragma unroll
            for (int q = 0; q < 4; q++) C[i][j][q] = 0.f;

    // A: 1024 chunks of 16B (4/thread): chunk c -> row c>>3, col (c&7)*8
    // B: 512 chunks of 16B (2/thread): chunk c -> row c>>3, col (c&7)*8
    auto issue_load = [&](int kt, int st) {
        int k0 = kt * BK;
        uint32_t sb = sbase + st * STG;
#pragma unroll
        for (int i = 0; i < 4; i++) {
            int c = tid + i * 256;
            int ar = c >> 3, ac = (c & 7) * 8;
            int gm = m0 + ar;
            int sz = (gm < M) ? 16 : 0;
            size_t ga = (size_t)gm * DHID + k0 + ac;
            uint32_t so = (uint32_t)(ar * LDA + ac) * 2;
            cpa16(sb + OFF_AH + so, &g_x_hi[ga], sz);
            cpa16(sb + OFF_AL + so, &g_x_lo[ga], sz);
        }
#pragma unroll
        for (int i = 0; i < 2; i++) {
            int c = tid + i * 256;
            int br = c >> 3, bc = (c & 7) * 8;
            size_t gb = (size_t)(k0 + br) * DHID + n0 + bc;
            uint32_t sob = (uint32_t)(br * LDB + bc) * 2;
            cpa16(sb + OFF_BH + sob, &g_w_hi[gb], 16);
            cpa16(sb + OFF_BL + sob, &g_w_lo[gb], 16);
        }
        CP_COMMIT();
    };

    issue_load(0, 0);

    const int NIT = DHID / BK;   // 16
    for (int kt = 0; kt < NIT; kt++) {
        // issue next stage (written into the buffer freed at end of iter kt-1)
        if (kt + 1 < NIT) issue_load(kt + 1, (kt + 1) & 1);
        else CP_COMMIT();
        CP_WAIT1();
        __syncthreads();

        uint32_t sb = sbase + (kt & 1) * STG;

#pragma unroll
        for (int ks = 0; ks < 4; ks++) {
            uint32_t Ah[2][4], Al[2][4], Bh[4][2], Bl[4][2];
#pragma unroll
            for (int mt = 0; mt < 2; mt++) {
                uint32_t off = ((wm * 32 + mt * 16 + lr) * LDA + ks * 16 + lc8) * 2;
                ldsm4(Ah[mt], sb + OFF_AH + off);
                ldsm4(Al[mt], sb + OFF_AL + off);
            }
#pragma unroll
            for (int nt2 = 0; nt2 < 2; nt2++) {
                uint32_t off = ((ks * 16 + lr) * LDB + wn * 32 + nt2 * 16 + lc8) * 2;
                uint32_t r[4];
                ldsm4t(r, sb + OFF_BH + off);
                Bh[nt2 * 2][0] = r[0]; Bh[nt2 * 2][1] = r[1];
                Bh[nt2 * 2 + 1][0] = r[2]; Bh[nt2 * 2 + 1][1] = r[3];
                ldsm4t(r, sb + OFF_BL + off);
                Bl[nt2 * 2][0] = r[0]; Bl[nt2 * 2][1] = r[1];
                Bl[nt2 * 2 + 1][0] = r[2]; Bl[nt2 * 2 + 1][1] = r[3];
            }
#pragma unroll
            for (int mt = 0; mt < 2; mt++)
#pragma unroll
                for (int nt = 0; nt < 4; nt++) {
                    mma16816(C[mt][nt], Ah[mt], Bh[nt]);
                    mma16816(C[mt][nt], Ah[mt], Bl[nt]);
                    mma16816(C[mt][nt], Al[mt], Bh[nt]);
                }
        }
        __syncthreads();
    }

    // ---- epilogue: store h + fused partial al/ar ----
    float av_l[8], av_r[8];
#pragma unroll
    for (int nt = 0; nt < 4; nt++) {
        int col = n0 + wn * 32 + nt * 8 + (lane & 3) * 2;
        av_l[nt * 2] = avec[col];        av_l[nt * 2 + 1] = avec[col + 1];
        av_r[nt * 2] = avec[DHID + col]; av_r[nt * 2 + 1] = avec[DHID + col + 1];
    }
#pragma unroll
    for (int mt = 0; mt < 2; mt++) {
        int row = m0 + wm * 32 + mt * 16 + (lane >> 2);
        float pl0 = 0.f, pr0 = 0.f, pl1 = 0.f, pr1 = 0.f;
#pragma unroll
        for (int nt = 0; nt < 4; nt++) {
            int col = n0 + wn * 32 + nt * 8 + (lane & 3) * 2;
            if (row < M) {
                float2 v = make_float2(C[mt][nt][0], C[mt][nt][1]);
                *(float2*)&g_h[(size_t)row * DHID + col] = v;
            }
            if (row + 8 < M) {
                float2 v = make_float2(C[mt][nt][2], C[mt][nt][3]);
                *(float2*)&g_h[(size_t)(row + 8) * DHID + col] = v;
            }
            pl0 += C[mt][nt][0] * av_l[nt * 2] + C[mt][nt][1] * av_l[nt * 2 + 1];
            pr0 += C[mt][nt][0] * av_r[nt * 2] + C[mt][nt][1] * av_r[nt * 2 + 1];
            pl1 += C[mt][nt][2] * av_l[nt * 2] + C[mt][nt][3] * av_l[nt * 2 + 1];
            pr1 += C[mt][nt][2] * av_r[nt * 2] + C[mt][nt][3] * av_r[nt * 2 + 1];
        }
#pragma unroll
        for (int o = 1; o < 4; o <<= 1) {
            pl0 += __shfl_xor_sync(0xffffffffu, pl0, o);
            pr0 += __shfl_xor_sync(0xffffffffu, pr0, o);
            pl1 += __shfl_xor_sync(0xffffffffu, pl1, o);
            pr1 += __shfl_xor_sync(0xffffffffu, pr1, o);
        }
        if ((lane & 3) == 0) {
            if (row < M)     { atomicAdd(&g_al[row], pl0);     atomicAdd(&g_ar[row], pr0); }
            if (row + 8 < M) { atomicAdd(&g_al[row + 8], pl1); atomicAdd(&g_ar[row + 8], pr1); }
        }
    }
}

// ---------------- exclusive scan: 10 elems/thread + shfl block scan ------
__global__ void scan_kernel(int N) {
    __shared__ int warp_tot[32];
    int tid = threadIdx.x;
    int lane = tid & 31, wrp = tid >> 5;
    int base = tid * 10;
    int loc[10];
    int s = 0;
#pragma unroll
    for (int q = 0; q < 10; q++) {
        int idx = base + q;
        int val = (idx < N) ? g_counts[idx] : 0;
        loc[q] = s;
        s += val;
    }
    int inc = s;
#pragma unroll
    for (int o = 1; o < 32; o <<= 1) {
        int t = __shfl_up_sync(0xffffffffu, inc, o);
        if (lane >= o) inc += t;
    }
    if (lane == 31) warp_tot[wrp] = inc;
    __syncthreads();
    if (wrp == 0) {
        int w = warp_tot[lane];
#pragma unroll
        for (int o = 1; o < 32; o <<= 1) {
            int t = __shfl_up_sync(0xffffffffu, w, o);
            if (lane >= o) w += t;
        }
        warp_tot[lane] = w;
    }
    __syncthreads();
    int warp_off = (wrp > 0) ? warp_tot[wrp - 1] : 0;
    int thr_excl = warp_off + inc - s;
#pragma unroll
    for (int q = 0; q < 10; q++) {
        int idx = base + q;
        if (idx < N) g_offsets[idx] = thr_excl + loc[q];
    }
    if (tid == 1023) g_offsets[N] = thr_excl + s;
}

// ---------------- edge weights + scatter into src-sorted order ----------
__global__ void scatter_kernel(int E) {
    int k = blockIdx.x * blockDim.x + threadIdx.x;
    if (k >= E) return;
    int s = g_src[k];
    int d = g_dst[k];
    float z = g_al[s] + g_ar[d];
    z = (z > 0.f) ? z : NEG_SLOPE * z;          // leaky_relu
    float ee = expf(-z);
    int pos = g_offsets[s] + atomicAdd(&g_cursor[s], 1);
    g_e_sorted[pos] = ee;
    g_dst_sorted[pos] = d;
}

// ---------------- CSR SpMM + normalize + ELU (one block / row) ----------
__global__ __launch_bounds__(256)
void spmm_kernel(float* __restrict__ out, int N) {
    int row = blockIdx.x;
    if (row >= N) return;
    int tid = threadIdx.x;
    int beg = g_offsets[row];
    int end = g_offsets[row + 1];

    __shared__ float se[256];
    __shared__ int   sd[256];

    float4 acc = make_float4(0.f, 0.f, 0.f, 0.f);
    float rs = 0.f;
    int c = tid * 4;

    for (int base = beg; base < end; base += 256) {
        int nload = end - base;
        if (nload > 256) nload = 256;
        if (tid < nload) {
            se[tid] = g_e_sorted[base + tid];
            sd[tid] = g_dst_sorted[base + tid];
        }
        __syncthreads();
        for (int j = 0; j < nload; j++) {
            float ev = se[j];
            int d = sd[j];
            float4 hv = *(const float4*)&g_h[(size_t)d * DHID + c];
            acc.x += ev * hv.x;
            acc.y += ev * hv.y;
            acc.z += ev * hv.z;
            acc.w += ev * hv.w;
            rs += ev;
        }
        __syncthreads();
    }

    float inv = 1.f / (rs + EPS_V);
    float v0 = acc.x * inv, v1 = acc.y * inv, v2 = acc.z * inv, v3 = acc.w * inv;
    float4 o;
    o.x = (v0 > 0.f) ? v0 : expm1f(v0);
    o.y = (v1 > 0.f) ? v1 : expm1f(v1);
    o.z = (v2 > 0.f) ? v2 : expm1f(v2);
    o.w = (v3 > 0.f) ? v3 : expm1f(v3);
    *(float4*)&out[(size_t)row * DHID + c] = o;
}

// ---------------- launch ----------------
extern "C" void kernel_launch(void* const* d_in, const int* in_sizes, int n_in,
                              void* d_out, int out_size) {
    const float* x = (const float*)d_in[0];
    const float* W = (const float*)d_in[1];
    const float* a = (const float*)d_in[2];
    const void* src = d_in[3];
    const void* dst = d_in[4];
    float* out = (float*)d_out;

    int N = in_sizes[0] / DHID;   // 10000
    int E = in_sizes[3];          // 160000
    if (N > MAXN) N = MAXN;
    if (E > MAXE) E = MAXE;

    init_kernel<<<(N + 255) / 256, 256>>>(N);      // launch 1
    detect_kernel<<<1, 256>>>(src, E, N);          // launch 2
    convert_kernel<<<(E + 255) / 256, 256>>>(src, dst, E);   // launch 3

    // prepass splits (launches 4, 5)
    {
        uint2* xh; uint2* xl; uint2* wh; uint2* wl;
        cudaGetSymbolAddress((void**)&xh, g_x_hi);
        cudaGetSymbolAddress((void**)&xl, g_x_lo);
        cudaGetSymbolAddress((void**)&wh, g_w_hi);
        cudaGetSymbolAddress((void**)&wl, g_w_lo);
        int n4x = N * DHID / 4;
        int n4w = DHID * DHID / 4;
        split_kernel<<<(n4x + 255) / 256, 256>>>((const float4*)x, xh, xl, n4x);
        split_kernel<<<(n4w + 255) / 256, 256>>>((const float4*)W, wh, wl, n4w);
    }

    cudaFuncSetAttribute(gemm_mma_kernel,
                         cudaFuncAttributeMaxDynamicSharedMemorySize, GEMM_SMEM);
    dim3 ggrid(DHID / BN, (N + BM - 1) / BM);
    gemm_mma_kernel<<<ggrid, 256, GEMM_SMEM>>>(a, N);   // launch 6 (ncu -s 5)

    scan_kernel<<<1, 1024>>>(N);                        // launch 7
    scatter_kernel<<<(E + 255) / 256, 256>>>(E);        // launch 8
    spmm_kernel<<<N, 256>>>(out, N);                    // launch 9
}

// round 12
// speedup vs baseline: 1.0034x; 1.0034x over previous
#include <cuda_runtime.h>
#include <cuda_bf16.h>
#include <math.h>
#include <stdint.h>

#define DHID 1024
#define MAXN 10240
#define MAXE 163840
#define NEG_SLOPE 0.1f
#define EPS_V 1e-5f

// ---------------- device scratch ----------------
__device__ float g_h[(size_t)MAXN * DHID];   // h = x @ W
__device__ __nv_bfloat16 g_x_hi[(size_t)MAXN * DHID];
__device__ __nv_bfloat16 g_x_lo[(size_t)MAXN * DHID];
__device__ __nv_bfloat16 g_w_hi[DHID * DHID];
__device__ __nv_bfloat16 g_w_lo[DHID * DHID];
__device__ float g_al[MAXN];
__device__ float g_ar[MAXN];
__device__ int   g_counts[MAXN];
__device__ int   g_cursor[MAXN];
__device__ int   g_offsets[MAXN + 1];
__device__ int   g_src[MAXE];
__device__ int   g_dst[MAXE];
__device__ int   g_dst_sorted[MAXE];
__device__ float g_e_sorted[MAXE];
__device__ int   g_is64;

__device__ __forceinline__ uint32_t smem_u32(const void* p) {
    uint32_t a;
    asm("{ .reg .u64 t; cvta.to.shared.u64 t, %1; cvt.u32.u64 %0, t; }" : "=r"(a) : "l"(p));
    return a;
}

__device__ __forceinline__ uint2 split_hi(float4 v, float4* rem) {
    __nv_bfloat16 h0 = __float2bfloat16(v.x);
    __nv_bfloat16 h1 = __float2bfloat16(v.y);
    __nv_bfloat16 h2 = __float2bfloat16(v.z);
    __nv_bfloat16 h3 = __float2bfloat16(v.w);
    rem->x = v.x - __bfloat162float(h0);
    rem->y = v.y - __bfloat162float(h1);
    rem->z = v.z - __bfloat162float(h2);
    rem->w = v.w - __bfloat162float(h3);
    uint2 u;
    u.x = (uint32_t)__bfloat16_as_ushort(h0) | ((uint32_t)__bfloat16_as_ushort(h1) << 16);
    u.y = (uint32_t)__bfloat16_as_ushort(h2) | ((uint32_t)__bfloat16_as_ushort(h3) << 16);
    return u;
}
__device__ __forceinline__ uint2 pack_bf16(float4 v) {
    uint2 u;
    u.x = (uint32_t)__bfloat16_as_ushort(__float2bfloat16(v.x)) |
          ((uint32_t)__bfloat16_as_ushort(__float2bfloat16(v.y)) << 16);
    u.y = (uint32_t)__bfloat16_as_ushort(__float2bfloat16(v.z)) |
          ((uint32_t)__bfloat16_as_ushort(__float2bfloat16(v.w)) << 16);
    return u;
}

// ---------------- fused init + dtype detect (launch 1) ----------------
__global__ void init_detect_kernel(const void* __restrict__ src, int E, int N) {
    int i = blockIdx.x * blockDim.x + threadIdx.x;
    if (i < N) { g_counts[i] = 0; g_cursor[i] = 0; g_al[i] = 0.f; g_ar[i] = 0.f; }
    if (blockIdx.x == 0) {
        if (threadIdx.x == 0) g_is64 = 1;
        __syncthreads();
        int n = E / 2; if (n > 4096) n = 4096;
        for (int k = threadIdx.x; k < n; k += blockDim.x) {
            long long v = ((const long long*)src)[k];
            if (v < 0 || v >= (long long)N) g_is64 = 0;
        }
    }
}

// convert + fused src histogram (after GEMM; feeds scan/scatter)
__global__ void convert_kernel(const void* __restrict__ src,
                               const void* __restrict__ dst, int E) {
    int k = blockIdx.x * blockDim.x + threadIdx.x;
    if (k >= E) return;
    int s, d;
    if (g_is64) {
        s = (int)((const long long*)src)[k];
        d = (int)((const long long*)dst)[k];
    } else {
        s = ((const int*)src)[k];
        d = ((const int*)dst)[k];
    }
    g_src[k] = s;
    g_dst[k] = d;
    atomicAdd(&g_counts[s], 1);
}

// ---------------- prepass: fp32 -> bf16 hi/lo split ----------------
__global__ void split_kernel(const float4* __restrict__ in,
                             uint2* __restrict__ hi, uint2* __restrict__ lo, int n4) {
    int i = blockIdx.x * blockDim.x + threadIdx.x;
    if (i >= n4) return;
    float4 v = in[i];
    float4 rem;
    uint2 uh = split_hi(v, &rem);
    uint2 ul = pack_bf16(rem);
    hi[i] = uh;
    lo[i] = ul;
}

// ================== tensor-core GEMM via mma.sync (HMMA) ==================
// h = x @ W, split-bf16 (hi*hi + hi*lo + lo*hi), fp32 accum.
// CTA tile 128x64, BK=32, 3-stage cp.async pipeline, 2 CTAs/SM.
// 8 warps, each 32x32 (2x4 m16n8k16 tiles). Fused al/ar epilogue.
// MMA issue order: term-major so consecutive MMAs never share an accumulator.
#define BM 128
#define BN 64
#define BK 32
#define LDA 40    // As row stride (bf16): 80B, conflict-free + 16B aligned
#define LDB 72    // Bs row stride (bf16): 144B

#define OFF_AH 0
#define OFF_AL (BM * LDA * 2)                 // 10240
#define OFF_BH (OFF_AL + BM * LDA * 2)        // 20480
#define OFF_BL (OFF_BH + BK * LDB * 2)        // 25088
#define STG    (OFF_BL + BK * LDB * 2)        // 29696 bytes / stage
#define STAGES 3
#define GEMM_SMEM (STAGES * STG)              // 89088 (x2 CTA = 178K < 228K)

__device__ __forceinline__ void mma16816(float* c, const uint32_t* a, const uint32_t* b) {
    asm volatile(
        "mma.sync.aligned.m16n8k16.row.col.f32.bf16.bf16.f32 "
        "{%0,%1,%2,%3}, {%4,%5,%6,%7}, {%8,%9}, {%0,%1,%2,%3};"
        : "+f"(c[0]), "+f"(c[1]), "+f"(c[2]), "+f"(c[3])
        : "r"(a[0]), "r"(a[1]), "r"(a[2]), "r"(a[3]), "r"(b[0]), "r"(b[1]));
}
__device__ __forceinline__ void ldsm4(uint32_t* r, uint32_t addr) {
    asm volatile("ldmatrix.sync.aligned.m8n8.x4.shared.b16 {%0,%1,%2,%3}, [%4];"
                 : "=r"(r[0]), "=r"(r[1]), "=r"(r[2]), "=r"(r[3]) : "r"(addr));
}
__device__ __forceinline__ void ldsm4t(uint32_t* r, uint32_t addr) {
    asm volatile("ldmatrix.sync.aligned.m8n8.x4.trans.shared.b16 {%0,%1,%2,%3}, [%4];"
                 : "=r"(r[0]), "=r"(r[1]), "=r"(r[2]), "=r"(r[3]) : "r"(addr));
}
__device__ __forceinline__ void cpa16(uint32_t s, const void* g, int sz) {
    asm volatile("cp.async.cg.shared.global [%0], [%1], 16, %2;"
                 :: "r"(s), "l"(g), "r"(sz) : "memory");
}
#define CP_COMMIT() asm volatile("cp.async.commit_group;" ::: "memory")
#define CP_WAIT2()  asm volatile("cp.async.wait_group 2;" ::: "memory")

__global__ __launch_bounds__(256, 2)
void gemm_mma_kernel(const float* __restrict__ avec, int M) {
    extern __shared__ __align__(16) char sm[];
    uint32_t sbase = smem_u32(sm);

    const int tid = threadIdx.x;
    const int lane = tid & 31;
    const int wid = tid >> 5;
    const int wm = wid & 3;          // 0..3 -> 32-row slab
    const int wn = wid >> 2;         // 0..1 -> 32-col slab
    const int m0 = blockIdx.y * BM;
    const int n0 = blockIdx.x * BN;

    const int lr = (lane & 7) + ((lane >> 3) & 1) * 8;
    const int lc8 = ((lane >> 4) & 1) * 8;

    float C[2][4][4];
#pragma unroll
    for (int i = 0; i < 2; i++)
#pragma unroll
        for (int j = 0; j < 4; j++)
#pragma unroll
            for (int q = 0; q < 4; q++) C[i][j][q] = 0.f;

    // A: 512 chunks of 16B (2/thread): chunk c -> row c>>2, col (c&3)*8
    // B: 256 chunks of 16B (1/thread): chunk c -> row c>>3, col (c&7)*8
    auto issue_load = [&](int kt, int st) {
        int k0 = kt * BK;
        uint32_t sb = sbase + st * STG;
#pragma unroll
        for (int i = 0; i < 2; i++) {
            int c = tid + i * 256;
            int ar = c >> 2, ac = (c & 3) * 8;
            int gm = m0 + ar;
            int sz = (gm < M) ? 16 : 0;
            size_t ga = (size_t)gm * DHID + k0 + ac;
            uint32_t so = (uint32_t)(ar * LDA + ac) * 2;
            cpa16(sb + OFF_AH + so, &g_x_hi[ga], sz);
            cpa16(sb + OFF_AL + so, &g_x_lo[ga], sz);
        }
        {
            int br = tid >> 3, bc = (tid & 7) * 8;
            size_t gb = (size_t)(k0 + br) * DHID + n0 + bc;
            uint32_t sob = (uint32_t)(br * LDB + bc) * 2;
            cpa16(sb + OFF_BH + sob, &g_w_hi[gb], 16);
            cpa16(sb + OFF_BL + sob, &g_w_lo[gb], 16);
        }
        CP_COMMIT();
    };

    issue_load(0, 0);
    issue_load(1, 1);

    const int NIT = DHID / BK;   // 32
    for (int kt = 0; kt < NIT; kt++) {
        if (kt + 2 < NIT) issue_load(kt + 2, (kt + 2) % STAGES);
        else CP_COMMIT();
        CP_WAIT2();
        __syncthreads();

        uint32_t sb = sbase + (kt % STAGES) * STG;

#pragma unroll
        for (int ks = 0; ks < 2; ks++) {
            uint32_t Ah[2][4], Al[2][4], Bh[4][2], Bl[4][2];
#pragma unroll
            for (int mt = 0; mt < 2; mt++) {
                uint32_t off = ((wm * 32 + mt * 16 + lr) * LDA + ks * 16 + lc8) * 2;
                ldsm4(Ah[mt], sb + OFF_AH + off);
                ldsm4(Al[mt], sb + OFF_AL + off);
            }
#pragma unroll
            for (int nt2 = 0; nt2 < 2; nt2++) {
                uint32_t off = ((ks * 16 + lr) * LDB + wn * 32 + nt2 * 16 + lc8) * 2;
                uint32_t r[4];
                ldsm4t(r, sb + OFF_BH + off);
                Bh[nt2 * 2][0] = r[0]; Bh[nt2 * 2][1] = r[1];
                Bh[nt2 * 2 + 1][0] = r[2]; Bh[nt2 * 2 + 1][1] = r[3];
                ldsm4t(r, sb + OFF_BL + off);
                Bl[nt2 * 2][0] = r[0]; Bl[nt2 * 2][1] = r[1];
                Bl[nt2 * 2 + 1][0] = r[2]; Bl[nt2 * 2 + 1][1] = r[3];
            }
            // term-major issue: consecutive MMAs target distinct accumulators
#pragma unroll
            for (int t = 0; t < 3; t++)
#pragma unroll
                for (int mt = 0; mt < 2; mt++)
#pragma unroll
                    for (int nt = 0; nt < 4; nt++)
                        mma16816(C[mt][nt],
                                 (t == 2) ? Al[mt] : Ah[mt],
                                 (t == 1) ? Bl[nt] : Bh[nt]);
        }
        __syncthreads();
    }

    // ---- epilogue: store h + fused partial al/ar ----
    float av_l[8], av_r[8];
#pragma unroll
    for (int nt = 0; nt < 4; nt++) {
        int col = n0 + wn * 32 + nt * 8 + (lane & 3) * 2;
        av_l[nt * 2] = avec[col];        av_l[nt * 2 + 1] = avec[col + 1];
        av_r[nt * 2] = avec[DHID + col]; av_r[nt * 2 + 1] = avec[DHID + col + 1];
    }
#pragma unroll
    for (int mt = 0; mt < 2; mt++) {
        int row = m0 + wm * 32 + mt * 16 + (lane >> 2);
        float pl0 = 0.f, pr0 = 0.f, pl1 = 0.f, pr1 = 0.f;
#pragma unroll
        for (int nt = 0; nt < 4; nt++) {
            int col = n0 + wn * 32 + nt * 8 + (lane & 3) * 2;
            if (row < M) {
                float2 v = make_float2(C[mt][nt][0], C[mt][nt][1]);
                *(float2*)&g_h[(size_t)row * DHID + col] = v;
            }
            if (row + 8 < M) {
                float2 v = make_float2(C[mt][nt][2], C[mt][nt][3]);
                *(float2*)&g_h[(size_t)(row + 8) * DHID + col] = v;
            }
            pl0 += C[mt][nt][0] * av_l[nt * 2] + C[mt][nt][1] * av_l[nt * 2 + 1];
            pr0 += C[mt][nt][0] * av_r[nt * 2] + C[mt][nt][1] * av_r[nt * 2 + 1];
            pl1 += C[mt][nt][2] * av_l[nt * 2] + C[mt][nt][3] * av_l[nt * 2 + 1];
            pr1 += C[mt][nt][2] * av_r[nt * 2] + C[mt][nt][3] * av_r[nt * 2 + 1];
        }
#pragma unroll
        for (int o = 1; o < 4; o <<= 1) {
            pl0 += __shfl_xor_sync(0xffffffffu, pl0, o);
            pr0 += __shfl_xor_sync(0xffffffffu, pr0, o);
            pl1 += __shfl_xor_sync(0xffffffffu, pl1, o);
            pr1 += __shfl_xor_sync(0xffffffffu, pr1, o);
        }
        if ((lane & 3) == 0) {
            if (row < M)     { atomicAdd(&g_al[row], pl0);     atomicAdd(&g_ar[row], pr0); }
            if (row + 8 < M) { atomicAdd(&g_al[row + 8], pl1); atomicAdd(&g_ar[row + 8], pr1); }
        }
    }
}

// ---------------- exclusive scan: 10 elems/thread + shfl block scan ------
__global__ void scan_kernel(int N) {
    __shared__ int warp_tot[32];
    int tid = threadIdx.x;
    int lane = tid & 31, wrp = tid >> 5;
    int base = tid * 10;
    int loc[10];
    int s = 0;
#pragma unroll
    for (int q = 0; q < 10; q++) {
        int idx = base + q;
        int val = (idx < N) ? g_counts[idx] : 0;
        loc[q] = s;
        s += val;
    }
    int inc = s;
#pragma unroll
    for (int o = 1; o < 32; o <<= 1) {
        int t = __shfl_up_sync(0xffffffffu, inc, o);
        if (lane >= o) inc += t;
    }
    if (lane == 31) warp_tot[wrp] = inc;
    __syncthreads();
    if (wrp == 0) {
        int w = warp_tot[lane];
#pragma unroll
        for (int o = 1; o < 32; o <<= 1) {
            int t = __shfl_up_sync(0xffffffffu, w, o);
            if (lane >= o) w += t;
        }
        warp_tot[lane] = w;
    }
    __syncthreads();
    int warp_off = (wrp > 0) ? warp_tot[wrp - 1] : 0;
    int thr_excl = warp_off + inc - s;
#pragma unroll
    for (int q = 0; q < 10; q++) {
        int idx = base + q;
        if (idx < N) g_offsets[idx] = thr_excl + loc[q];
    }
    if (tid == 1023) g_offsets[N] = thr_excl + s;
}

// ---------------- edge weights + scatter into src-sorted order ----------
__global__ void scatter_kernel(int E) {
    int k = blockIdx.x * blockDim.x + threadIdx.x;
    if (k >= E) return;
    int s = g_src[k];
    int d = g_dst[k];
    float z = g_al[s] + g_ar[d];
    z = (z > 0.f) ? z : NEG_SLOPE * z;          // leaky_relu
    float ee = expf(-z);
    int pos = g_offsets[s] + atomicAdd(&g_cursor[s], 1);
    g_e_sorted[pos] = ee;
    g_dst_sorted[pos] = d;
}

// ---------------- CSR SpMM + normalize + ELU (one block / row) ----------
__global__ __launch_bounds__(256)
void spmm_kernel(float* __restrict__ out, int N) {
    int row = blockIdx.x;
    if (row >= N) return;
    int tid = threadIdx.x;
    int beg = g_offsets[row];
    int end = g_offsets[row + 1];

    __shared__ float se[256];
    __shared__ int   sd[256];

    float4 acc = make_float4(0.f, 0.f, 0.f, 0.f);
    float rs = 0.f;
    int c = tid * 4;

    for (int base = beg; base < end; base += 256) {
        int nload = end - base;
        if (nload > 256) nload = 256;
        if (tid < nload) {
            se[tid] = g_e_sorted[base + tid];
            sd[tid] = g_dst_sorted[base + tid];
        }
        __syncthreads();
        for (int j = 0; j < nload; j++) {
            float ev = se[j];
            int d = sd[j];
            float4 hv = *(const float4*)&g_h[(size_t)d * DHID + c];
            acc.x += ev * hv.x;
            acc.y += ev * hv.y;
            acc.z += ev * hv.z;
            acc.w += ev * hv.w;
            rs += ev;
        }
        __syncthreads();
    }

    float inv = 1.f / (rs + EPS_V);
    float v0 = acc.x * inv, v1 = acc.y * inv, v2 = acc.z * inv, v3 = acc.w * inv;
    float4 o;
    o.x = (v0 > 0.f) ? v0 : expm1f(v0);
    o.y = (v1 > 0.f) ? v1 : expm1f(v1);
    o.z = (v2 > 0.f) ? v2 : expm1f(v2);
    o.w = (v3 > 0.f) ? v3 : expm1f(v3);
    *(float4*)&out[(size_t)row * DHID + c] = o;
}

// ---------------- launch ----------------
extern "C" void kernel_launch(void* const* d_in, const int* in_sizes, int n_in,
                              void* d_out, int out_size) {
    const float* x = (const float*)d_in[0];
    const float* W = (const float*)d_in[1];
    const float* a = (const float*)d_in[2];
    const void* src = d_in[3];
    const void* dst = d_in[4];
    float* out = (float*)d_out;

    int N = in_sizes[0] / DHID;   // 10000
    int E = in_sizes[3];          // 160000
    if (N > MAXN) N = MAXN;
    if (E > MAXE) E = MAXE;

    init_detect_kernel<<<(N + 255) / 256, 256>>>(src, E, N);   // launch 1

    // prepass splits (launches 2, 3)
    {
        uint2* xh; uint2* xl; uint2* wh; uint2* wl;
        cudaGetSymbolAddress((void**)&xh, g_x_hi);
        cudaGetSymbolAddress((void**)&xl, g_x_lo);
        cudaGetSymbolAddress((void**)&wh, g_w_hi);
        cudaGetSymbolAddress((void**)&wl, g_w_lo);
        int n4x = N * DHID / 4;
        int n4w = DHID * DHID / 4;
        split_kernel<<<(n4x + 255) / 256, 256>>>((const float4*)x, xh, xl, n4x);
        split_kernel<<<(n4w + 255) / 256, 256>>>((const float4*)W, wh, wl, n4w);
    }

    cudaFuncSetAttribute(gemm_mma_kernel,
                         cudaFuncAttributeMaxDynamicSharedMemorySize, GEMM_SMEM);
    dim3 ggrid(DHID / BN, (N + BM - 1) / BM);
    gemm_mma_kernel<<<ggrid, 256, GEMM_SMEM>>>(a, N);          // launch 4 (ncu)

    convert_kernel<<<(E + 255) / 256, 256>>>(src, dst, E);     // launch 5
    scan_kernel<<<1, 1024>>>(N);                               // launch 6
    scatter_kernel<<<(E + 255) / 256, 256>>>(E);               // launch 7
    spmm_kernel<<<N, 256>>>(out, N);                           // launch 8
}

// round 13
// speedup vs baseline: 1.1417x; 1.1378x over previous
#include <cuda_runtime.h>
#include <cuda_bf16.h>
#include <math.h>
#include <stdint.h>

#define DHID 1024
#define MAXN 10240
#define MAXE 163840
#define NEG_SLOPE 0.1f
#define EPS_V 1e-5f

// ---------------- device scratch ----------------
__device__ float g_h[(size_t)MAXN * DHID];   // h = x @ W
__device__ float g_xr[(size_t)MAXN * DHID];  // tf32-rounded x
__device__ float g_wt[DHID * DHID];          // tf32-rounded W^T (n-major)
__device__ float g_al[MAXN];
__device__ float g_ar[MAXN];
__device__ int   g_counts[MAXN];
__device__ int   g_cursor[MAXN];
__device__ int   g_offsets[MAXN + 1];
__device__ int   g_src[MAXE];
__device__ int   g_dst[MAXE];
__device__ int   g_dst_sorted[MAXE];
__device__ float g_e_sorted[MAXE];
__device__ int   g_is64;

__device__ __forceinline__ uint32_t smem_u32(const void* p) {
    uint32_t a;
    asm("{ .reg .u64 t; cvta.to.shared.u64 t, %1; cvt.u32.u64 %0, t; }" : "=r"(a) : "l"(p));
    return a;
}
__device__ __forceinline__ float tf32r(float v) {
    uint32_t o;
    asm("cvt.rna.tf32.f32 %0, %1;" : "=r"(o) : "f"(v));
    return __uint_as_float(o);
}

// ---------------- fused init + dtype detect (launch 1) ----------------
__global__ void init_detect_kernel(const void* __restrict__ src, int E, int N) {
    int i = blockIdx.x * blockDim.x + threadIdx.x;
    if (i < N) { g_counts[i] = 0; g_cursor[i] = 0; g_al[i] = 0.f; g_ar[i] = 0.f; }
    if (blockIdx.x == 0) {
        if (threadIdx.x == 0) g_is64 = 1;
        __syncthreads();
        int n = E / 2; if (n > 4096) n = 4096;
        for (int k = threadIdx.x; k < n; k += blockDim.x) {
            long long v = ((const long long*)src)[k];
            if (v < 0 || v >= (long long)N) g_is64 = 0;
        }
    }
}

// ---------------- prepass: x -> tf32-rounded (launch 2) ----------------
__global__ void round_x_kernel(const float4* __restrict__ in, float4* __restrict__ o, int n4) {
    int i = blockIdx.x * blockDim.x + threadIdx.x;
    if (i >= n4) return;
    float4 v = in[i];
    o[i] = make_float4(tf32r(v.x), tf32r(v.y), tf32r(v.z), tf32r(v.w));
}

// ---------------- prepass: W -> transposed + tf32-rounded (launch 3) ----
__global__ void wt_round_kernel(const float* __restrict__ W) {
    __shared__ float t[32][33];
    int bx = blockIdx.x * 32;   // n block
    int by = blockIdx.y * 32;   // k block
    for (int j = threadIdx.y; j < 32; j += 8)
        t[j][threadIdx.x] = W[(size_t)(by + j) * DHID + bx + threadIdx.x];
    __syncthreads();
    for (int j = threadIdx.y; j < 32; j += 8)
        g_wt[(size_t)(bx + j) * DHID + by + threadIdx.x] = tf32r(t[threadIdx.x][j]);
}

// ================== tensor-core GEMM via mma.sync tf32 ==================
// h = x @ W, single-pass tf32 (rna pre-rounded), fp32 accum.
// CTA tile 128x64, BK=32, 3-stage cp.async pipeline, 2 CTAs/SM.
// 8 warps, each 32x32 = 2x4 m16n8k8 tiles x 4 k-steps.
#define BM 128
#define BN 64
#define BK 32
#define LDAF 36    // A row stride in floats (144B): ldmatrix conflict-free
#define LDBF 36    // B row stride in floats (144B)

#define OFF_B  (BM * LDAF * 4)                // 18432
#define STG    (OFF_B + BN * LDBF * 4)        // 27648 bytes / stage
#define STAGES 3
#define GEMM_SMEM (STAGES * STG)              // 82944 (x2 CTA = 166K < 228K)

__device__ __forceinline__ void mma_tf32(float* c, const uint32_t* a, const uint32_t* b) {
    asm volatile(
        "mma.sync.aligned.m16n8k8.row.col.f32.tf32.tf32.f32 "
        "{%0,%1,%2,%3}, {%4,%5,%6,%7}, {%8,%9}, {%0,%1,%2,%3};"
        : "+f"(c[0]), "+f"(c[1]), "+f"(c[2]), "+f"(c[3])
        : "r"(a[0]), "r"(a[1]), "r"(a[2]), "r"(a[3]), "r"(b[0]), "r"(b[1]));
}
__device__ __forceinline__ void ldsm4(uint32_t* r, uint32_t addr) {
    asm volatile("ldmatrix.sync.aligned.m8n8.x4.shared.b16 {%0,%1,%2,%3}, [%4];"
                 : "=r"(r[0]), "=r"(r[1]), "=r"(r[2]), "=r"(r[3]) : "r"(addr));
}
__device__ __forceinline__ void cpa16(uint32_t s, const void* g, int sz) {
    asm volatile("cp.async.cg.shared.global [%0], [%1], 16, %2;"
                 :: "r"(s), "l"(g), "r"(sz) : "memory");
}
#define CP_COMMIT() asm volatile("cp.async.commit_group;" ::: "memory")
#define CP_WAIT2()  asm volatile("cp.async.wait_group 2;" ::: "memory")

__global__ __launch_bounds__(256, 2)
void gemm_mma_kernel(const float* __restrict__ avec, int M) {
    extern __shared__ __align__(16) char sm[];
    uint32_t sbase = smem_u32(sm);

    const int tid = threadIdx.x;
    const int lane = tid & 31;
    const int wid = tid >> 5;
    const int wm = wid & 3;          // 0..3 -> 32-row slab
    const int wn = wid >> 2;         // 0..1 -> 32-col slab
    const int m0 = blockIdx.y * BM;
    const int n0 = blockIdx.x * BN;

    // ldmatrix addressing
    // A (per mt, ks): row = m_tile + (lane&7) + ((lane>>3)&1)*8 ; colf = ks*8 + (lane>>4)*4
    const int a_lr  = (lane & 7) + ((lane >> 3) & 1) * 8;
    const int a_lc4 = ((lane >> 4) & 1) * 4;
    // B (per pair p, ks): row = nb(p) + (lane&7) + ((lane>>4)&1)*8 ; colf = ks*8 + ((lane>>3)&1)*4
    const int b_lr  = (lane & 7) + ((lane >> 4) & 1) * 8;
    const int b_lc4 = ((lane >> 3) & 1) * 4;

    float C[2][4][4];
#pragma unroll
    for (int i = 0; i < 2; i++)
#pragma unroll
        for (int j = 0; j < 4; j++)
#pragma unroll
            for (int q = 0; q < 4; q++) C[i][j][q] = 0.f;

    // A: 1024 chunks of 16B (4/thread): chunk c -> row c>>3, colf (c&7)*4
    // B: 512 chunks of 16B (2/thread): chunk c -> nrow c>>3, colf (c&7)*4
    auto issue_load = [&](int kt, int st) {
        int k0 = kt * BK;
        uint32_t sb = sbase + st * STG;
#pragma unroll
        for (int i = 0; i < 4; i++) {
            int c = tid + i * 256;
            int ar = c >> 3, ac = (c & 7) * 4;
            int gm = m0 + ar;
            int sz = (gm < M) ? 16 : 0;
            cpa16(sb + (uint32_t)(ar * LDAF + ac) * 4,
                  &g_xr[(size_t)gm * DHID + k0 + ac], sz);
        }
#pragma unroll
        for (int i = 0; i < 2; i++) {
            int c = tid + i * 256;
            int br = c >> 3, bc = (c & 7) * 4;
            cpa16(sb + OFF_B + (uint32_t)(br * LDBF + bc) * 4,
                  &g_wt[(size_t)(n0 + br) * DHID + k0 + bc], 16);
        }
        CP_COMMIT();
    };

    issue_load(0, 0);
    issue_load(1, 1);

    const int NIT = DHID / BK;   // 32
    for (int kt = 0; kt < NIT; kt++) {
        if (kt + 2 < NIT) issue_load(kt + 2, (kt + 2) % STAGES);
        else CP_COMMIT();
        CP_WAIT2();
        __syncthreads();

        uint32_t sb = sbase + (kt % STAGES) * STG;

#pragma unroll
        for (int ks = 0; ks < 4; ks++) {
            uint32_t Af[2][4], Bf[4][2];
#pragma unroll
            for (int mt = 0; mt < 2; mt++) {
                uint32_t off = ((wm * 32 + mt * 16 + a_lr) * LDAF + ks * 8 + a_lc4) * 4;
                ldsm4(Af[mt], sb + off);
            }
#pragma unroll
            for (int p = 0; p < 2; p++) {
                uint32_t off = ((wn * 32 + p * 16 + b_lr) * LDBF + ks * 8 + b_lc4) * 4;
                uint32_t r[4];
                ldsm4(r, sb + OFF_B + off);
                Bf[p * 2][0] = r[0];     Bf[p * 2][1] = r[1];
                Bf[p * 2 + 1][0] = r[2]; Bf[p * 2 + 1][1] = r[3];
            }
#pragma unroll
            for (int mt = 0; mt < 2; mt++)
#pragma unroll
                for (int nt = 0; nt < 4; nt++)
                    mma_tf32(C[mt][nt], Af[mt], Bf[nt]);
        }
        __syncthreads();
    }

    // ---- epilogue: store h + fused partial al/ar ----
    float av_l[8], av_r[8];
#pragma unroll
    for (int nt = 0; nt < 4; nt++) {
        int col = n0 + wn * 32 + nt * 8 + (lane & 3) * 2;
        av_l[nt * 2] = avec[col];        av_l[nt * 2 + 1] = avec[col + 1];
        av_r[nt * 2] = avec[DHID + col]; av_r[nt * 2 + 1] = avec[DHID + col + 1];
    }
#pragma unroll
    for (int mt = 0; mt < 2; mt++) {
        int row = m0 + wm * 32 + mt * 16 + (lane >> 2);
        float pl0 = 0.f, pr0 = 0.f, pl1 = 0.f, pr1 = 0.f;
#pragma unroll
        for (int nt = 0; nt < 4; nt++) {
            int col = n0 + wn * 32 + nt * 8 + (lane & 3) * 2;
            if (row < M) {
                float2 v = make_float2(C[mt][nt][0], C[mt][nt][1]);
                *(float2*)&g_h[(size_t)row * DHID + col] = v;
            }
            if (row + 8 < M) {
                float2 v = make_float2(C[mt][nt][2], C[mt][nt][3]);
                *(float2*)&g_h[(size_t)(row + 8) * DHID + col] = v;
            }
            pl0 += C[mt][nt][0] * av_l[nt * 2] + C[mt][nt][1] * av_l[nt * 2 + 1];
            pr0 += C[mt][nt][0] * av_r[nt * 2] + C[mt][nt][1] * av_r[nt * 2 + 1];
            pl1 += C[mt][nt][2] * av_l[nt * 2] + C[mt][nt][3] * av_l[nt * 2 + 1];
            pr1 += C[mt][nt][2] * av_r[nt * 2] + C[mt][nt][3] * av_r[nt * 2 + 1];
        }
#pragma unroll
        for (int o = 1; o < 4; o <<= 1) {
            pl0 += __shfl_xor_sync(0xffffffffu, pl0, o);
            pr0 += __shfl_xor_sync(0xffffffffu, pr0, o);
            pl1 += __shfl_xor_sync(0xffffffffu, pl1, o);
            pr1 += __shfl_xor_sync(0xffffffffu, pr1, o);
        }
        if ((lane & 3) == 0) {
            if (row < M)     { atomicAdd(&g_al[row], pl0);     atomicAdd(&g_ar[row], pr0); }
            if (row + 8 < M) { atomicAdd(&g_al[row + 8], pl1); atomicAdd(&g_ar[row + 8], pr1); }
        }
    }
}

// convert + fused src histogram (after GEMM; feeds scan/scatter)
__global__ void convert_kernel(const void* __restrict__ src,
                               const void* __restrict__ dst, int E) {
    int k = blockIdx.x * blockDim.x + threadIdx.x;
    if (k >= E) return;
    int s, d;
    if (g_is64) {
        s = (int)((const long long*)src)[k];
        d = (int)((const long long*)dst)[k];
    } else {
        s = ((const int*)src)[k];
        d = ((const int*)dst)[k];
    }
    g_src[k] = s;
    g_dst[k] = d;
    atomicAdd(&g_counts[s], 1);
}

// ---------------- exclusive scan: 10 elems/thread + shfl block scan ------
__global__ void scan_kernel(int N) {
    __shared__ int warp_tot[32];
    int tid = threadIdx.x;
    int lane = tid & 31, wrp = tid >> 5;
    int base = tid * 10;
    int loc[10];
    int s = 0;
#pragma unroll
    for (int q = 0; q < 10; q++) {
        int idx = base + q;
        int val = (idx < N) ? g_counts[idx] : 0;
        loc[q] = s;
        s += val;
    }
    int inc = s;
#pragma unroll
    for (int o = 1; o < 32; o <<= 1) {
        int t = __shfl_up_sync(0xffffffffu, inc, o);
        if (lane >= o) inc += t;
    }
    if (lane == 31) warp_tot[wrp] = inc;
    __syncthreads();
    if (wrp == 0) {
        int w = warp_tot[lane];
#pragma unroll
        for (int o = 1; o < 32; o <<= 1) {
            int t = __shfl_up_sync(0xffffffffu, w, o);
            if (lane >= o) w += t;
        }
        warp_tot[lane] = w;
    }
    __syncthreads();
    int warp_off = (wrp > 0) ? warp_tot[wrp - 1] : 0;
    int thr_excl = warp_off + inc - s;
#pragma unroll
    for (int q = 0; q < 10; q++) {
        int idx = base + q;
        if (idx < N) g_offsets[idx] = thr_excl + loc[q];
    }
    if (tid == 1023) g_offsets[N] = thr_excl + s;
}

// ---------------- edge weights + scatter into src-sorted order ----------
__global__ void scatter_kernel(int E) {
    int k = blockIdx.x * blockDim.x + threadIdx.x;
    if (k >= E) return;
    int s = g_src[k];
    int d = g_dst[k];
    float z = g_al[s] + g_ar[d];
    z = (z > 0.f) ? z : NEG_SLOPE * z;          // leaky_relu
    float ee = expf(-z);
    int pos = g_offsets[s] + atomicAdd(&g_cursor[s], 1);
    g_e_sorted[pos] = ee;
    g_dst_sorted[pos] = d;
}

// ---------------- CSR SpMM + normalize + ELU (one block / row) ----------
__global__ __launch_bounds__(256)
void spmm_kernel(float* __restrict__ out, int N) {
    int row = blockIdx.x;
    if (row >= N) return;
    int tid = threadIdx.x;
    int beg = g_offsets[row];
    int end = g_offsets[row + 1];

    __shared__ float se[256];
    __shared__ int   sd[256];

    float4 acc = make_float4(0.f, 0.f, 0.f, 0.f);
    float rs = 0.f;
    int c = tid * 4;

    for (int base = beg; base < end; base += 256) {
        int nload = end - base;
        if (nload > 256) nload = 256;
        if (tid < nload) {
            se[tid] = g_e_sorted[base + tid];
            sd[tid] = g_dst_sorted[base + tid];
        }
        __syncthreads();
        for (int j = 0; j < nload; j++) {
            float ev = se[j];
            int d = sd[j];
            float4 hv = *(const float4*)&g_h[(size_t)d * DHID + c];
            acc.x += ev * hv.x;
            acc.y += ev * hv.y;
            acc.z += ev * hv.z;
            acc.w += ev * hv.w;
            rs += ev;
        }
        __syncthreads();
    }

    float inv = 1.f / (rs + EPS_V);
    float v0 = acc.x * inv, v1 = acc.y * inv, v2 = acc.z * inv, v3 = acc.w * inv;
    float4 o;
    o.x = (v0 > 0.f) ? v0 : expm1f(v0);
    o.y = (v1 > 0.f) ? v1 : expm1f(v1);
    o.z = (v2 > 0.f) ? v2 : expm1f(v2);
    o.w = (v3 > 0.f) ? v3 : expm1f(v3);
    *(float4*)&out[(size_t)row * DHID + c] = o;
}

// ---------------- launch ----------------
extern "C" void kernel_launch(void* const* d_in, const int* in_sizes, int n_in,
                              void* d_out, int out_size) {
    const float* x = (const float*)d_in[0];
    const float* W = (const float*)d_in[1];
    const float* a = (const float*)d_in[2];
    const void* src = d_in[3];
    const void* dst = d_in[4];
    float* out = (float*)d_out;

    int N = in_sizes[0] / DHID;   // 10000
    int E = in_sizes[3];          // 160000
    if (N > MAXN) N = MAXN;
    if (E > MAXE) E = MAXE;

    init_detect_kernel<<<(N + 255) / 256, 256>>>(src, E, N);   // launch 1

    {
        float4* xr;
        cudaGetSymbolAddress((void**)&xr, g_xr);
        int n4x = N * DHID / 4;
        round_x_kernel<<<(n4x + 255) / 256, 256>>>((const float4*)x, xr, n4x);  // 2
    }
    wt_round_kernel<<<dim3(DHID / 32, DHID / 32), dim3(32, 8)>>>(W);            // 3

    cudaFuncSetAttribute(gemm_mma_kernel,
                         cudaFuncAttributeMaxDynamicSharedMemorySize, GEMM_SMEM);
    dim3 ggrid(DHID / BN, (N + BM - 1) / BM);
    gemm_mma_kernel<<<ggrid, 256, GEMM_SMEM>>>(a, N);          // launch 4 (ncu)

    convert_kernel<<<(E + 255) / 256, 256>>>(src, dst, E);     // launch 5
    scan_kernel<<<1, 1024>>>(N);                               // launch 6
    scatter_kernel<<<(E + 255) / 256, 256>>>(E);               // launch 7
    spmm_kernel<<<N, 256>>>(out, N);                           // launch 8
}

// round 14
// speedup vs baseline: 1.2249x; 1.0729x over previous
#include <cuda_runtime.h>
#include <cuda_bf16.h>
#include <math.h>
#include <stdint.h>

#define DHID 1024
#define MAXN 10240
#define MAXE 163840
#define NEG_SLOPE 0.1f
#define EPS_V 1e-5f

// ---------------- device scratch ----------------
__device__ float g_h[(size_t)MAXN * DHID];   // h = x @ W
__device__ float g_xr[(size_t)MAXN * DHID];  // tf32-rounded x
__device__ float g_wt[DHID * DHID];          // tf32-rounded W^T (n-major)
__device__ float g_al[MAXN];
__device__ float g_ar[MAXN];
__device__ int   g_counts[MAXN];
__device__ int   g_cursor[MAXN];
__device__ int   g_offsets[MAXN + 1];
__device__ int   g_src[MAXE];
__device__ int   g_dst[MAXE];
__device__ int   g_dst_sorted[MAXE];
__device__ float g_e_sorted[MAXE];
__device__ int   g_is64;

__device__ __forceinline__ uint32_t smem_u32(const void* p) {
    uint32_t a;
    asm("{ .reg .u64 t; cvta.to.shared.u64 t, %1; cvt.u32.u64 %0, t; }" : "=r"(a) : "l"(p));
    return a;
}
__device__ __forceinline__ float tf32r(float v) {
    uint32_t o;
    asm("cvt.rna.tf32.f32 %0, %1;" : "=r"(o) : "f"(v));
    return __uint_as_float(o);
}

// ---------------- fused init + dtype detect (launch 1) ----------------
__global__ void init_detect_kernel(const void* __restrict__ src, int E, int N) {
    int i = blockIdx.x * blockDim.x + threadIdx.x;
    if (i < N) { g_counts[i] = 0; g_cursor[i] = 0; g_al[i] = 0.f; g_ar[i] = 0.f; }
    if (blockIdx.x == 0) {
        if (threadIdx.x == 0) g_is64 = 1;
        __syncthreads();
        int n = E / 2; if (n > 4096) n = 4096;
        for (int k = threadIdx.x; k < n; k += blockDim.x) {
            long long v = ((const long long*)src)[k];
            if (v < 0 || v >= (long long)N) g_is64 = 0;
        }
    }
}

// ---------------- prepass: x -> tf32-rounded (launch 2) ----------------
__global__ void round_x_kernel(const float4* __restrict__ in, float4* __restrict__ o, int n4) {
    int i = blockIdx.x * blockDim.x + threadIdx.x;
    if (i >= n4) return;
    float4 v = in[i];
    o[i] = make_float4(tf32r(v.x), tf32r(v.y), tf32r(v.z), tf32r(v.w));
}

// ---------------- prepass: W -> transposed + tf32-rounded (launch 3) ----
__global__ void wt_round_kernel(const float* __restrict__ W) {
    __shared__ float t[32][33];
    int bx = blockIdx.x * 32;   // n block
    int by = blockIdx.y * 32;   // k block
    for (int j = threadIdx.y; j < 32; j += 8)
        t[j][threadIdx.x] = W[(size_t)(by + j) * DHID + bx + threadIdx.x];
    __syncthreads();
    for (int j = threadIdx.y; j < 32; j += 8)
        g_wt[(size_t)(bx + j) * DHID + by + threadIdx.x] = tf32r(t[threadIdx.x][j]);
}

// ================== tensor-core GEMM via mma.sync tf32 ==================
// h = x @ W, single-pass tf32 (rna pre-rounded), fp32 accum.
// CTA tile 128x128, BK=32, 3-stage cp.async pipeline, 2 CTAs/SM.
// 8 warps, each 64x32 = 4x4 m16n8k8 tiles x 4 k-steps (6 LDSM / 16 MMA).
#define BM 128
#define BN 128
#define BK 32
#define LDAF 36    // A row stride in floats (144B): ldmatrix conflict-free
#define LDBF 36    // B row stride in floats (144B)

#define OFF_B  (BM * LDAF * 4)                // 18432
#define STG    (OFF_B + BN * LDBF * 4)        // 36864 bytes / stage
#define STAGES 3
#define GEMM_SMEM (STAGES * STG)              // 110592 (x2 CTA = 221K < 228K)

__device__ __forceinline__ void mma_tf32(float* c, const uint32_t* a, const uint32_t* b) {
    asm volatile(
        "mma.sync.aligned.m16n8k8.row.col.f32.tf32.tf32.f32 "
        "{%0,%1,%2,%3}, {%4,%5,%6,%7}, {%8,%9}, {%0,%1,%2,%3};"
        : "+f"(c[0]), "+f"(c[1]), "+f"(c[2]), "+f"(c[3])
        : "r"(a[0]), "r"(a[1]), "r"(a[2]), "r"(a[3]), "r"(b[0]), "r"(b[1]));
}
__device__ __forceinline__ void ldsm4(uint32_t* r, uint32_t addr) {
    asm volatile("ldmatrix.sync.aligned.m8n8.x4.shared.b16 {%0,%1,%2,%3}, [%4];"
                 : "=r"(r[0]), "=r"(r[1]), "=r"(r[2]), "=r"(r[3]) : "r"(addr));
}
__device__ __forceinline__ void cpa16(uint32_t s, const void* g, int sz) {
    asm volatile("cp.async.cg.shared.global [%0], [%1], 16, %2;"
                 :: "r"(s), "l"(g), "r"(sz) : "memory");
}
#define CP_COMMIT() asm volatile("cp.async.commit_group;" ::: "memory")
#define CP_WAIT2()  asm volatile("cp.async.wait_group 2;" ::: "memory")

__global__ __launch_bounds__(256, 2)
void gemm_mma_kernel(const float* __restrict__ avec, int M) {
    extern __shared__ __align__(16) char sm[];
    uint32_t sbase = smem_u32(sm);

    const int tid = threadIdx.x;
    const int lane = tid & 31;
    const int wid = tid >> 5;
    const int wm = wid & 1;          // 0..1 -> 64-row slab
    const int wn = wid >> 1;         // 0..3 -> 32-col slab
    const int m0 = blockIdx.y * BM;
    const int n0 = blockIdx.x * BN;

    // ldmatrix addressing
    const int a_lr  = (lane & 7) + ((lane >> 3) & 1) * 8;
    const int a_lc4 = ((lane >> 4) & 1) * 4;
    const int b_lr  = (lane & 7) + ((lane >> 4) & 1) * 8;
    const int b_lc4 = ((lane >> 3) & 1) * 4;

    float C[4][4][4];
#pragma unroll
    for (int i = 0; i < 4; i++)
#pragma unroll
        for (int j = 0; j < 4; j++)
#pragma unroll
            for (int q = 0; q < 4; q++) C[i][j][q] = 0.f;

    // A: 1024 chunks of 16B (4/thread): chunk c -> row c>>3, colf (c&7)*4
    // B: 1024 chunks of 16B (4/thread): same mapping
    auto issue_load = [&](int kt, int st) {
        int k0 = kt * BK;
        uint32_t sb = sbase + st * STG;
#pragma unroll
        for (int i = 0; i < 4; i++) {
            int c = tid + i * 256;
            int ar = c >> 3, ac = (c & 7) * 4;
            int gm = m0 + ar;
            int sz = (gm < M) ? 16 : 0;
            cpa16(sb + (uint32_t)(ar * LDAF + ac) * 4,
                  &g_xr[(size_t)gm * DHID + k0 + ac], sz);
        }
#pragma unroll
        for (int i = 0; i < 4; i++) {
            int c = tid + i * 256;
            int br = c >> 3, bc = (c & 7) * 4;
            cpa16(sb + OFF_B + (uint32_t)(br * LDBF + bc) * 4,
                  &g_wt[(size_t)(n0 + br) * DHID + k0 + bc], 16);
        }
        CP_COMMIT();
    };

    issue_load(0, 0);
    issue_load(1, 1);

    const int NIT = DHID / BK;   // 32
    for (int kt = 0; kt < NIT; kt++) {
        if (kt + 2 < NIT) issue_load(kt + 2, (kt + 2) % STAGES);
        else CP_COMMIT();
        CP_WAIT2();
        __syncthreads();

        uint32_t sb = sbase + (kt % STAGES) * STG;

#pragma unroll
        for (int ks = 0; ks < 4; ks++) {
            uint32_t Af[4][4], Bf[4][2];
#pragma unroll
            for (int mt = 0; mt < 4; mt++) {
                uint32_t off = ((wm * 64 + mt * 16 + a_lr) * LDAF + ks * 8 + a_lc4) * 4;
                ldsm4(Af[mt], sb + off);
            }
#pragma unroll
            for (int p = 0; p < 2; p++) {
                uint32_t off = ((wn * 32 + p * 16 + b_lr) * LDBF + ks * 8 + b_lc4) * 4;
                uint32_t r[4];
                ldsm4(r, sb + OFF_B + off);
                Bf[p * 2][0] = r[0];     Bf[p * 2][1] = r[1];
                Bf[p * 2 + 1][0] = r[2]; Bf[p * 2 + 1][1] = r[3];
            }
#pragma unroll
            for (int mt = 0; mt < 4; mt++)
#pragma unroll
                for (int nt = 0; nt < 4; nt++)
                    mma_tf32(C[mt][nt], Af[mt], Bf[nt]);
        }
        __syncthreads();
    }

    // ---- epilogue: store h + fused partial al/ar ----
    float av_l[8], av_r[8];
#pragma unroll
    for (int nt = 0; nt < 4; nt++) {
        int col = n0 + wn * 32 + nt * 8 + (lane & 3) * 2;
        av_l[nt * 2] = avec[col];        av_l[nt * 2 + 1] = avec[col + 1];
        av_r[nt * 2] = avec[DHID + col]; av_r[nt * 2 + 1] = avec[DHID + col + 1];
    }
#pragma unroll
    for (int mt = 0; mt < 4; mt++) {
        int row = m0 + wm * 64 + mt * 16 + (lane >> 2);
        float pl0 = 0.f, pr0 = 0.f, pl1 = 0.f, pr1 = 0.f;
#pragma unroll
        for (int nt = 0; nt < 4; nt++) {
            int col = n0 + wn * 32 + nt * 8 + (lane & 3) * 2;
            if (row < M) {
                float2 v = make_float2(C[mt][nt][0], C[mt][nt][1]);
                *(float2*)&g_h[(size_t)row * DHID + col] = v;
            }
            if (row + 8 < M) {
                float2 v = make_float2(C[mt][nt][2], C[mt][nt][3]);
                *(float2*)&g_h[(size_t)(row + 8) * DHID + col] = v;
            }
            pl0 += C[mt][nt][0] * av_l[nt * 2] + C[mt][nt][1] * av_l[nt * 2 + 1];
            pr0 += C[mt][nt][0] * av_r[nt * 2] + C[mt][nt][1] * av_r[nt * 2 + 1];
            pl1 += C[mt][nt][2] * av_l[nt * 2] + C[mt][nt][3] * av_l[nt * 2 + 1];
            pr1 += C[mt][nt][2] * av_r[nt * 2] + C[mt][nt][3] * av_r[nt * 2 + 1];
        }
#pragma unroll
        for (int o = 1; o < 4; o <<= 1) {
            pl0 += __shfl_xor_sync(0xffffffffu, pl0, o);
            pr0 += __shfl_xor_sync(0xffffffffu, pr0, o);
            pl1 += __shfl_xor_sync(0xffffffffu, pl1, o);
            pr1 += __shfl_xor_sync(0xffffffffu, pr1, o);
        }
        if ((lane & 3) == 0) {
            if (row < M)     { atomicAdd(&g_al[row], pl0);     atomicAdd(&g_ar[row], pr0); }
            if (row + 8 < M) { atomicAdd(&g_al[row + 8], pl1); atomicAdd(&g_ar[row + 8], pr1); }
        }
    }
}

// convert + fused src histogram (after GEMM; feeds scan/scatter)
__global__ void convert_kernel(const void* __restrict__ src,
                               const void* __restrict__ dst, int E) {
    int k = blockIdx.x * blockDim.x + threadIdx.x;
    if (k >= E) return;
    int s, d;
    if (g_is64) {
        s = (int)((const long long*)src)[k];
        d = (int)((const long long*)dst)[k];
    } else {
        s = ((const int*)src)[k];
        d = ((const int*)dst)[k];
    }
    g_src[k] = s;
    g_dst[k] = d;
    atomicAdd(&g_counts[s], 1);
}

// ---------------- exclusive scan: 10 elems/thread + shfl block scan ------
__global__ void scan_kernel(int N) {
    __shared__ int warp_tot[32];
    int tid = threadIdx.x;
    int lane = tid & 31, wrp = tid >> 5;
    int base = tid * 10;
    int loc[10];
    int s = 0;
#pragma unroll
    for (int q = 0; q < 10; q++) {
        int idx = base + q;
        int val = (idx < N) ? g_counts[idx] : 0;
        loc[q] = s;
        s += val;
    }
    int inc = s;
#pragma unroll
    for (int o = 1; o < 32; o <<= 1) {
        int t = __shfl_up_sync(0xffffffffu, inc, o);
        if (lane >= o) inc += t;
    }
    if (lane == 31) warp_tot[wrp] = inc;
    __syncthreads();
    if (wrp == 0) {
        int w = warp_tot[lane];
#pragma unroll
        for (int o = 1; o < 32; o <<= 1) {
            int t = __shfl_up_sync(0xffffffffu, w, o);
            if (lane >= o) w += t;
        }
        warp_tot[lane] = w;
    }
    __syncthreads();
    int warp_off = (wrp > 0) ? warp_tot[wrp - 1] : 0;
    int thr_excl = warp_off + inc - s;
#pragma unroll
    for (int q = 0; q < 10; q++) {
        int idx = base + q;
        if (idx < N) g_offsets[idx] = thr_excl + loc[q];
    }
    if (tid == 1023) g_offsets[N] = thr_excl + s;
}

// ---------------- edge weights + scatter into src-sorted order ----------
__global__ void scatter_kernel(int E) {
    int k = blockIdx.x * blockDim.x + threadIdx.x;
    if (k >= E) return;
    int s = g_src[k];
    int d = g_dst[k];
    float z = g_al[s] + g_ar[d];
    z = (z > 0.f) ? z : NEG_SLOPE * z;          // leaky_relu
    float ee = expf(-z);
    int pos = g_offsets[s] + atomicAdd(&g_cursor[s], 1);
    g_e_sorted[pos] = ee;
    g_dst_sorted[pos] = d;
}

// ---------------- CSR SpMM + normalize + ELU (one block / row) ----------
__global__ __launch_bounds__(256)
void spmm_kernel(float* __restrict__ out, int N) {
    int row = blockIdx.x;
    if (row >= N) return;
    int tid = threadIdx.x;
    int beg = g_offsets[row];
    int end = g_offsets[row + 1];

    __shared__ float se[256];
    __shared__ int   sd[256];

    float4 acc = make_float4(0.f, 0.f, 0.f, 0.f);
    float rs = 0.f;
    int c = tid * 4;

    for (int base = beg; base < end; base += 256) {
        int nload = end - base;
        if (nload > 256) nload = 256;
        if (tid < nload) {
            se[tid] = g_e_sorted[base + tid];
            sd[tid] = g_dst_sorted[base + tid];
        }
        __syncthreads();
        for (int j = 0; j < nload; j++) {
            float ev = se[j];
            int d = sd[j];
            float4 hv = *(const float4*)&g_h[(size_t)d * DHID + c];
            acc.x += ev * hv.x;
            acc.y += ev * hv.y;
            acc.z += ev * hv.z;
            acc.w += ev * hv.w;
            rs += ev;
        }
        __syncthreads();
    }

    float inv = 1.f / (rs + EPS_V);
    float v0 = acc.x * inv, v1 = acc.y * inv, v2 = acc.z * inv, v3 = acc.w * inv;
    float4 o;
    o.x = (v0 > 0.f) ? v0 : expm1f(v0);
    o.y = (v1 > 0.f) ? v1 : expm1f(v1);
    o.z = (v2 > 0.f) ? v2 : expm1f(v2);
    o.w = (v3 > 0.f) ? v3 : expm1f(v3);
    *(float4*)&out[(size_t)row * DHID + c] = o;
}

// ---------------- launch ----------------
extern "C" void kernel_launch(void* const* d_in, const int* in_sizes, int n_in,
                              void* d_out, int out_size) {
    const float* x = (const float*)d_in[0];
    const float* W = (const float*)d_in[1];
    const float* a = (const float*)d_in[2];
    const void* src = d_in[3];
    const void* dst = d_in[4];
    float* out = (float*)d_out;

    int N = in_sizes[0] / DHID;   // 10000
    int E = in_sizes[3];          // 160000
    if (N > MAXN) N = MAXN;
    if (E > MAXE) E = MAXE;

    init_detect_kernel<<<(N + 255) / 256, 256>>>(src, E, N);   // launch 1

    {
        float4* xr;
        cudaGetSymbolAddress((void**)&xr, g_xr);
        int n4x = N * DHID / 4;
        round_x_kernel<<<(n4x + 255) / 256, 256>>>((const float4*)x, xr, n4x);  // 2
    }
    wt_round_kernel<<<dim3(DHID / 32, DHID / 32), dim3(32, 8)>>>(W);            // 3

    cudaFuncSetAttribute(gemm_mma_kernel,
                         cudaFuncAttributeMaxDynamicSharedMemorySize, GEMM_SMEM);
    dim3 ggrid(DHID / BN, (N + BM - 1) / BM);
    gemm_mma_kernel<<<ggrid, 256, GEMM_SMEM>>>(a, N);          // launch 4 (ncu)

    convert_kernel<<<(E + 255) / 256, 256>>>(src, dst, E);     // launch 5
    scan_kernel<<<1, 1024>>>(N);                               // launch 6
    scatter_kernel<<<(E + 255) / 256, 256>>>(E);               // launch 7
    spmm_kernel<<<N, 256>>>(out, N);                           // launch 8
}

// round 15
// speedup vs baseline: 1.2925x; 1.0552x over previous
#include <cuda_runtime.h>
#include <cuda_bf16.h>
#include <math.h>
#include <stdint.h>

#define DHID 1024
#define MAXN 10240
#define MAXE 163840
#define NEG_SLOPE 0.1f
#define EPS_V 1e-5f

// ---------------- device scratch ----------------
__device__ float g_h[(size_t)MAXN * DHID];   // h = x @ W
__device__ float g_wt[DHID * DHID];          // tf32-rounded W^T (n-major)
__device__ float g_al[MAXN];
__device__ float g_ar[MAXN];
__device__ int   g_counts[MAXN];
__device__ int   g_cursor[MAXN];
__device__ int   g_offsets[MAXN + 1];
__device__ int   g_src[MAXE];
__device__ int   g_dst[MAXE];
__device__ int   g_dst_sorted[MAXE];
__device__ float g_e_sorted[MAXE];
__device__ int   g_is64;

__device__ __forceinline__ uint32_t smem_u32(const void* p) {
    uint32_t a;
    asm("{ .reg .u64 t; cvta.to.shared.u64 t, %1; cvt.u32.u64 %0, t; }" : "=r"(a) : "l"(p));
    return a;
}
__device__ __forceinline__ float tf32r(float v) {
    uint32_t o;
    asm("cvt.rna.tf32.f32 %0, %1;" : "=r"(o) : "f"(v));
    return __uint_as_float(o);
}
__device__ __forceinline__ uint32_t tf32r_u(uint32_t bits) {
    uint32_t o;
    asm("cvt.rna.tf32.f32 %0, %1;" : "=r"(o) : "f"(__uint_as_float(bits)));
    return o;
}

// ---------------- fused init + dtype detect ----------------
__global__ void init_detect_kernel(const void* __restrict__ src, int E, int N) {
    int i = blockIdx.x * blockDim.x + threadIdx.x;
    if (i < N) { g_counts[i] = 0; g_cursor[i] = 0; g_al[i] = 0.f; g_ar[i] = 0.f; }
    if (blockIdx.x == 0) {
        if (threadIdx.x == 0) g_is64 = 1;
        __syncthreads();
        int n = E / 2; if (n > 4096) n = 4096;
        for (int k = threadIdx.x; k < n; k += blockDim.x) {
            long long v = ((const long long*)src)[k];
            if (v < 0 || v >= (long long)N) g_is64 = 0;
        }
    }
}

// ---------------- prepass: W -> transposed + tf32-rounded ----------------
__global__ void wt_round_kernel(const float* __restrict__ W) {
    __shared__ float t[32][33];
    int bx = blockIdx.x * 32;   // n block
    int by = blockIdx.y * 32;   // k block
    for (int j = threadIdx.y; j < 32; j += 8)
        t[j][threadIdx.x] = W[(size_t)(by + j) * DHID + bx + threadIdx.x];
    __syncthreads();
    for (int j = threadIdx.y; j < 32; j += 8)
        g_wt[(size_t)(bx + j) * DHID + by + threadIdx.x] = tf32r(t[threadIdx.x][j]);
}

// ================== tensor-core GEMM via mma.sync tf32 ==================
// h = x @ W, single-pass tf32, fp32 accum. A loaded raw and rounded
// (cvt.rna) on fragments post-ldmatrix; B (W^T) pre-rounded.
// CTA tile 128x128, BK=32, 3-stage cp.async pipeline, 2 CTAs/SM.
// 8 warps, each 64x32 = 4x4 m16n8k8 tiles x 4 k-steps.
#define BM 128
#define BN 128
#define BK 32
#define LDAF 36    // A row stride in floats (144B): ldmatrix conflict-free
#define LDBF 36

#define OFF_B  (BM * LDAF * 4)                // 18432
#define STG    (OFF_B + BN * LDBF * 4)        // 36864 bytes / stage
#define STAGES 3
#define GEMM_SMEM (STAGES * STG)              // 110592 (x2 CTA = 221K < 228K)

__device__ __forceinline__ void mma_tf32(float* c, const uint32_t* a, const uint32_t* b) {
    asm volatile(
        "mma.sync.aligned.m16n8k8.row.col.f32.tf32.tf32.f32 "
        "{%0,%1,%2,%3}, {%4,%5,%6,%7}, {%8,%9}, {%0,%1,%2,%3};"
        : "+f"(c[0]), "+f"(c[1]), "+f"(c[2]), "+f"(c[3])
        : "r"(a[0]), "r"(a[1]), "r"(a[2]), "r"(a[3]), "r"(b[0]), "r"(b[1]));
}
__device__ __forceinline__ void ldsm4(uint32_t* r, uint32_t addr) {
    asm volatile("ldmatrix.sync.aligned.m8n8.x4.shared.b16 {%0,%1,%2,%3}, [%4];"
                 : "=r"(r[0]), "=r"(r[1]), "=r"(r[2]), "=r"(r[3]) : "r"(addr));
}
__device__ __forceinline__ void cpa16(uint32_t s, const void* g, int sz) {
    asm volatile("cp.async.cg.shared.global [%0], [%1], 16, %2;"
                 :: "r"(s), "l"(g), "r"(sz) : "memory");
}
#define CP_COMMIT() asm volatile("cp.async.commit_group;" ::: "memory")
#define CP_WAIT2()  asm volatile("cp.async.wait_group 2;" ::: "memory")

__global__ __launch_bounds__(256, 2)
void gemm_mma_kernel(const float* __restrict__ xin, const float* __restrict__ avec, int M) {
    extern __shared__ __align__(16) char sm[];
    uint32_t sbase = smem_u32(sm);

    const int tid = threadIdx.x;
    const int lane = tid & 31;
    const int wid = tid >> 5;
    const int wm = wid & 1;          // 0..1 -> 64-row slab
    const int wn = wid >> 1;         // 0..3 -> 32-col slab
    const int m0 = blockIdx.y * BM;
    const int n0 = blockIdx.x * BN;

    const int a_lr  = (lane & 7) + ((lane >> 3) & 1) * 8;
    const int a_lc4 = ((lane >> 4) & 1) * 4;
    const int b_lr  = (lane & 7) + ((lane >> 4) & 1) * 8;
    const int b_lc4 = ((lane >> 3) & 1) * 4;

    float C[4][4][4];
#pragma unroll
    for (int i = 0; i < 4; i++)
#pragma unroll
        for (int j = 0; j < 4; j++)
#pragma unroll
            for (int q = 0; q < 4; q++) C[i][j][q] = 0.f;

    auto issue_load = [&](int kt, int st) {
        int k0 = kt * BK;
        uint32_t sb = sbase + st * STG;
#pragma unroll
        for (int i = 0; i < 4; i++) {
            int c = tid + i * 256;
            int ar = c >> 3, ac = (c & 7) * 4;
            int gm = m0 + ar;
            int sz = (gm < M) ? 16 : 0;
            cpa16(sb + (uint32_t)(ar * LDAF + ac) * 4,
                  &xin[(size_t)gm * DHID + k0 + ac], sz);
        }
#pragma unroll
        for (int i = 0; i < 4; i++) {
            int c = tid + i * 256;
            int br = c >> 3, bc = (c & 7) * 4;
            cpa16(sb + OFF_B + (uint32_t)(br * LDBF + bc) * 4,
                  &g_wt[(size_t)(n0 + br) * DHID + k0 + bc], 16);
        }
        CP_COMMIT();
    };

    issue_load(0, 0);
    issue_load(1, 1);

    const int NIT = DHID / BK;   // 32
    for (int kt = 0; kt < NIT; kt++) {
        if (kt + 2 < NIT) issue_load(kt + 2, (kt + 2) % STAGES);
        else CP_COMMIT();
        CP_WAIT2();
        __syncthreads();

        uint32_t sb = sbase + (kt % STAGES) * STG;

#pragma unroll
        for (int ks = 0; ks < 4; ks++) {
            uint32_t Af[4][4], Bf[4][2];
#pragma unroll
            for (int mt = 0; mt < 4; mt++) {
                uint32_t off = ((wm * 64 + mt * 16 + a_lr) * LDAF + ks * 8 + a_lc4) * 4;
                ldsm4(Af[mt], sb + off);
            }
#pragma unroll
            for (int p = 0; p < 2; p++) {
                uint32_t off = ((wn * 32 + p * 16 + b_lr) * LDBF + ks * 8 + b_lc4) * 4;
                uint32_t r[4];
                ldsm4(r, sb + OFF_B + off);
                Bf[p * 2][0] = r[0];     Bf[p * 2][1] = r[1];
                Bf[p * 2 + 1][0] = r[2]; Bf[p * 2 + 1][1] = r[3];
            }
            // round raw x fragments to tf32 (rna)
#pragma unroll
            for (int mt = 0; mt < 4; mt++)
#pragma unroll
                for (int q = 0; q < 4; q++) Af[mt][q] = tf32r_u(Af[mt][q]);
#pragma unroll
            for (int mt = 0; mt < 4; mt++)
#pragma unroll
                for (int nt = 0; nt < 4; nt++)
                    mma_tf32(C[mt][nt], Af[mt], Bf[nt]);
        }
        __syncthreads();
    }

    // ---- epilogue: store h + fused partial al/ar ----
    float av_l[8], av_r[8];
#pragma unroll
    for (int nt = 0; nt < 4; nt++) {
        int col = n0 + wn * 32 + nt * 8 + (lane & 3) * 2;
        av_l[nt * 2] = avec[col];        av_l[nt * 2 + 1] = avec[col + 1];
        av_r[nt * 2] = avec[DHID + col]; av_r[nt * 2 + 1] = avec[DHID + col + 1];
    }
#pragma unroll
    for (int mt = 0; mt < 4; mt++) {
        int row = m0 + wm * 64 + mt * 16 + (lane >> 2);
        float pl0 = 0.f, pr0 = 0.f, pl1 = 0.f, pr1 = 0.f;
#pragma unroll
        for (int nt = 0; nt < 4; nt++) {
            int col = n0 + wn * 32 + nt * 8 + (lane & 3) * 2;
            if (row < M) {
                float2 v = make_float2(C[mt][nt][0], C[mt][nt][1]);
                *(float2*)&g_h[(size_t)row * DHID + col] = v;
            }
            if (row + 8 < M) {
                float2 v = make_float2(C[mt][nt][2], C[mt][nt][3]);
                *(float2*)&g_h[(size_t)(row + 8) * DHID + col] = v;
            }
            pl0 += C[mt][nt][0] * av_l[nt * 2] + C[mt][nt][1] * av_l[nt * 2 + 1];
            pr0 += C[mt][nt][0] * av_r[nt * 2] + C[mt][nt][1] * av_r[nt * 2 + 1];
            pl1 += C[mt][nt][2] * av_l[nt * 2] + C[mt][nt][3] * av_l[nt * 2 + 1];
            pr1 += C[mt][nt][2] * av_r[nt * 2] + C[mt][nt][3] * av_r[nt * 2 + 1];
        }
#pragma unroll
        for (int o = 1; o < 4; o <<= 1) {
            pl0 += __shfl_xor_sync(0xffffffffu, pl0, o);
            pr0 += __shfl_xor_sync(0xffffffffu, pr0, o);
            pl1 += __shfl_xor_sync(0xffffffffu, pl1, o);
            pr1 += __shfl_xor_sync(0xffffffffu, pr1, o);
        }
        if ((lane & 3) == 0) {
            if (row < M)     { atomicAdd(&g_al[row], pl0);     atomicAdd(&g_ar[row], pr0); }
            if (row + 8 < M) { atomicAdd(&g_al[row + 8], pl1); atomicAdd(&g_ar[row + 8], pr1); }
        }
    }
}

// convert + fused src histogram
__global__ void convert_kernel(const void* __restrict__ src,
                               const void* __restrict__ dst, int E) {
    int k = blockIdx.x * blockDim.x + threadIdx.x;
    if (k >= E) return;
    int s, d;
    if (g_is64) {
        s = (int)((const long long*)src)[k];
        d = (int)((const long long*)dst)[k];
    } else {
        s = ((const int*)src)[k];
        d = ((const int*)dst)[k];
    }
    g_src[k] = s;
    g_dst[k] = d;
    atomicAdd(&g_counts[s], 1);
}

// ---------------- exclusive scan: 10 elems/thread + shfl block scan ------
__global__ void scan_kernel(int N) {
    __shared__ int warp_tot[32];
    int tid = threadIdx.x;
    int lane = tid & 31, wrp = tid >> 5;
    int base = tid * 10;
    int loc[10];
    int s = 0;
#pragma unroll
    for (int q = 0; q < 10; q++) {
        int idx = base + q;
        int val = (idx < N) ? g_counts[idx] : 0;
        loc[q] = s;
        s += val;
    }
    int inc = s;
#pragma unroll
    for (int o = 1; o < 32; o <<= 1) {
        int t = __shfl_up_sync(0xffffffffu, inc, o);
        if (lane >= o) inc += t;
    }
    if (lane == 31) warp_tot[wrp] = inc;
    __syncthreads();
    if (wrp == 0) {
        int w = warp_tot[lane];
#pragma unroll
        for (int o = 1; o < 32; o <<= 1) {
            int t = __shfl_up_sync(0xffffffffu, w, o);
            if (lane >= o) w += t;
        }
        warp_tot[lane] = w;
    }
    __syncthreads();
    int warp_off = (wrp > 0) ? warp_tot[wrp - 1] : 0;
    int thr_excl = warp_off + inc - s;
#pragma unroll
    for (int q = 0; q < 10; q++) {
        int idx = base + q;
        if (idx < N) g_offsets[idx] = thr_excl + loc[q];
    }
    if (tid == 1023) g_offsets[N] = thr_excl + s;
}

// ---------------- edge weights + scatter into src-sorted order ----------
__global__ void scatter_kernel(int E) {
    int k = blockIdx.x * blockDim.x + threadIdx.x;
    if (k >= E) return;
    int s = g_src[k];
    int d = g_dst[k];
    float z = g_al[s] + g_ar[d];
    z = (z > 0.f) ? z : NEG_SLOPE * z;          // leaky_relu
    float ee = expf(-z);
    int pos = g_offsets[s] + atomicAdd(&g_cursor[s], 1);
    g_e_sorted[pos] = ee;
    g_dst_sorted[pos] = d;
}

// ---------------- CSR SpMM + normalize + ELU (one block / row) ----------
__global__ __launch_bounds__(256)
void spmm_kernel(float* __restrict__ out, int N) {
    int row = blockIdx.x;
    if (row >= N) return;
    int tid = threadIdx.x;
    int beg = g_offsets[row];
    int end = g_offsets[row + 1];

    __shared__ float se[256];
    __shared__ int   sd[256];

    float4 acc = make_float4(0.f, 0.f, 0.f, 0.f);
    float rs = 0.f;
    int c = tid * 4;

    for (int base = beg; base < end; base += 256) {
        int nload = end - base;
        if (nload > 256) nload = 256;
        if (tid < nload) {
            se[tid] = g_e_sorted[base + tid];
            sd[tid] = g_dst_sorted[base + tid];
        }
        __syncthreads();
        for (int j = 0; j < nload; j++) {
            float ev = se[j];
            int d = sd[j];
            float4 hv = *(const float4*)&g_h[(size_t)d * DHID + c];
            acc.x += ev * hv.x;
            acc.y += ev * hv.y;
            acc.z += ev * hv.z;
            acc.w += ev * hv.w;
            rs += ev;
        }
        __syncthreads();
    }

    float inv = 1.f / (rs + EPS_V);
    float v0 = acc.x * inv, v1 = acc.y * inv, v2 = acc.z * inv, v3 = acc.w * inv;
    float4 o;
    o.x = (v0 > 0.f) ? v0 : expm1f(v0);
    o.y = (v1 > 0.f) ? v1 : expm1f(v1);
    o.z = (v2 > 0.f) ? v2 : expm1f(v2);
    o.w = (v3 > 0.f) ? v3 : expm1f(v3);
    *(float4*)&out[(size_t)row * DHID + c] = o;
}

// ---------------- launch ----------------
extern "C" void kernel_launch(void* const* d_in, const int* in_sizes, int n_in,
                              void* d_out, int out_size) {
    const float* x = (const float*)d_in[0];
    const float* W = (const float*)d_in[1];
    const float* a = (const float*)d_in[2];
    const void* src = d_in[3];
    const void* dst = d_in[4];
    float* out = (float*)d_out;

    int N = in_sizes[0] / DHID;   // 10000
    int E = in_sizes[3];          // 160000
    if (N > MAXN) N = MAXN;
    if (E > MAXE) E = MAXE;

    // host-side handles, created once (no device memory involved)
    static cudaStream_t s2 = 0;
    static cudaEvent_t ev_fork = 0, ev_join = 0;
    if (!s2) {
        cudaStreamCreateWithFlags(&s2, cudaStreamNonBlocking);
        cudaEventCreateWithFlags(&ev_fork, cudaEventDisableTiming);
        cudaEventCreateWithFlags(&ev_join, cudaEventDisableTiming);
        cudaFuncSetAttribute(gemm_mma_kernel,
                             cudaFuncAttributeMaxDynamicSharedMemorySize, GEMM_SMEM);
    }

    init_detect_kernel<<<(N + 255) / 256, 256>>>(src, E, N);

    // fork: edge prelude runs concurrently with W-prep + GEMM
    cudaEventRecord(ev_fork, 0);
    cudaStreamWaitEvent(s2, ev_fork, 0);

    wt_round_kernel<<<dim3(DHID / 32, DHID / 32), dim3(32, 8)>>>(W);
    dim3 ggrid(DHID / BN, (N + BM - 1) / BM);
    gemm_mma_kernel<<<ggrid, 256, GEMM_SMEM>>>(x, a, N);

    convert_kernel<<<(E + 255) / 256, 256, 0, s2>>>(src, dst, E);
    scan_kernel<<<1, 1024, 0, s2>>>(N);
    cudaEventRecord(ev_join, s2);

    // join: scatter needs GEMM's al/ar (stream 0) and scan's offsets (s2)
    cudaStreamWaitEvent(0, ev_join, 0);
    scatter_kernel<<<(E + 255) / 256, 256>>>(E);
    spmm_kernel<<<N, 256>>>(out, N);
}

// round 16
// speedup vs baseline: 1.3704x; 1.0602x over previous
#include <cuda_runtime.h>
#include <cuda_bf16.h>
#include <cuda_fp16.h>
#include <math.h>
#include <stdint.h>

#define DHID 1024
#define MAXN 10240
#define MAXE 163840
#define NEG_SLOPE 0.1f
#define EPS_V 1e-5f

// ---------------- device scratch ----------------
__device__ __half g_hh[(size_t)MAXN * DHID]; // h = x @ W (fp16, spmm-only)
__device__ float g_wt[DHID * DHID];          // tf32-rounded W^T (n-major)
__device__ float g_al[MAXN];
__device__ float g_ar[MAXN];
__device__ int   g_counts[MAXN];
__device__ int   g_cursor[MAXN];
__device__ int   g_offsets[MAXN + 1];
__device__ int   g_src[MAXE];
__device__ int   g_dst[MAXE];
__device__ int   g_dst_sorted[MAXE];
__device__ float g_e_sorted[MAXE];
__device__ int   g_is64;

__device__ __forceinline__ uint32_t smem_u32(const void* p) {
    uint32_t a;
    asm("{ .reg .u64 t; cvta.to.shared.u64 t, %1; cvt.u32.u64 %0, t; }" : "=r"(a) : "l"(p));
    return a;
}
__device__ __forceinline__ float tf32r(float v) {
    uint32_t o;
    asm("cvt.rna.tf32.f32 %0, %1;" : "=r"(o) : "f"(v));
    return __uint_as_float(o);
}
__device__ __forceinline__ uint32_t tf32r_u(uint32_t bits) {
    uint32_t o;
    asm("cvt.rna.tf32.f32 %0, %1;" : "=r"(o) : "f"(__uint_as_float(bits)));
    return o;
}

// ---------------- fused init + dtype detect ----------------
__global__ void init_detect_kernel(const void* __restrict__ src, int E, int N) {
    int i = blockIdx.x * blockDim.x + threadIdx.x;
    if (i < N) { g_counts[i] = 0; g_cursor[i] = 0; g_al[i] = 0.f; g_ar[i] = 0.f; }
    if (blockIdx.x == 0) {
        if (threadIdx.x == 0) g_is64 = 1;
        __syncthreads();
        int n = E / 2; if (n > 4096) n = 4096;
        for (int k = threadIdx.x; k < n; k += blockDim.x) {
            long long v = ((const long long*)src)[k];
            if (v < 0 || v >= (long long)N) g_is64 = 0;
        }
    }
}

// ---------------- prepass: W -> transposed + tf32-rounded ----------------
__global__ void wt_round_kernel(const float* __restrict__ W) {
    __shared__ float t[32][33];
    int bx = blockIdx.x * 32;   // n block
    int by = blockIdx.y * 32;   // k block
    for (int j = threadIdx.y; j < 32; j += 8)
        t[j][threadIdx.x] = W[(size_t)(by + j) * DHID + bx + threadIdx.x];
    __syncthreads();
    for (int j = threadIdx.y; j < 32; j += 8)
        g_wt[(size_t)(bx + j) * DHID + by + threadIdx.x] = tf32r(t[threadIdx.x][j]);
}

// ================== tensor-core GEMM via mma.sync tf32 ==================
// h = x @ W, single-pass tf32, fp32 accum. A loaded raw and rounded
// (cvt.rna) post-ldmatrix; B (W^T) pre-rounded.
// CTA tile 128x128, BK=32, 3-stage cp.async pipeline, 2 CTAs/SM.
// 8 warps, each 64x32. Fused al/ar epilogue; h stored as fp16.
#define BM 128
#define BN 128
#define BK 32
#define LDAF 36
#define LDBF 36

#define OFF_B  (BM * LDAF * 4)                // 18432
#define STG    (OFF_B + BN * LDBF * 4)        // 36864 bytes / stage
#define STAGES 3
#define GEMM_SMEM (STAGES * STG)              // 110592 (x2 CTA = 221K)

__device__ __forceinline__ void mma_tf32(float* c, const uint32_t* a, const uint32_t* b) {
    asm volatile(
        "mma.sync.aligned.m16n8k8.row.col.f32.tf32.tf32.f32 "
        "{%0,%1,%2,%3}, {%4,%5,%6,%7}, {%8,%9}, {%0,%1,%2,%3};"
        : "+f"(c[0]), "+f"(c[1]), "+f"(c[2]), "+f"(c[3])
        : "r"(a[0]), "r"(a[1]), "r"(a[2]), "r"(a[3]), "r"(b[0]), "r"(b[1]));
}
__device__ __forceinline__ void ldsm4(uint32_t* r, uint32_t addr) {
    asm volatile("ldmatrix.sync.aligned.m8n8.x4.shared.b16 {%0,%1,%2,%3}, [%4];"
                 : "=r"(r[0]), "=r"(r[1]), "=r"(r[2]), "=r"(r[3]) : "r"(addr));
}
__device__ __forceinline__ void cpa16(uint32_t s, const void* g, int sz) {
    asm volatile("cp.async.cg.shared.global [%0], [%1], 16, %2;"
                 :: "r"(s), "l"(g), "r"(sz) : "memory");
}
#define CP_COMMIT() asm volatile("cp.async.commit_group;" ::: "memory")
#define CP_WAIT2()  asm volatile("cp.async.wait_group 2;" ::: "memory")

__global__ __launch_bounds__(256, 2)
void gemm_mma_kernel(const float* __restrict__ xin, const float* __restrict__ avec, int M) {
    extern __shared__ __align__(16) char sm[];
    uint32_t sbase = smem_u32(sm);

    const int tid = threadIdx.x;
    const int lane = tid & 31;
    const int wid = tid >> 5;
    const int wm = wid & 1;          // 0..1 -> 64-row slab
    const int wn = wid >> 1;         // 0..3 -> 32-col slab
    const int m0 = blockIdx.y * BM;
    const int n0 = blockIdx.x * BN;

    const int a_lr  = (lane & 7) + ((lane >> 3) & 1) * 8;
    const int a_lc4 = ((lane >> 4) & 1) * 4;
    const int b_lr  = (lane & 7) + ((lane >> 4) & 1) * 8;
    const int b_lc4 = ((lane >> 3) & 1) * 4;

    float C[4][4][4];
#pragma unroll
    for (int i = 0; i < 4; i++)
#pragma unroll
        for (int j = 0; j < 4; j++)
#pragma unroll
            for (int q = 0; q < 4; q++) C[i][j][q] = 0.f;

    auto issue_load = [&](int kt, int st) {
        int k0 = kt * BK;
        uint32_t sb = sbase + st * STG;
#pragma unroll
        for (int i = 0; i < 4; i++) {
            int c = tid + i * 256;
            int ar = c >> 3, ac = (c & 7) * 4;
            int gm = m0 + ar;
            int sz = (gm < M) ? 16 : 0;
            cpa16(sb + (uint32_t)(ar * LDAF + ac) * 4,
                  &xin[(size_t)gm * DHID + k0 + ac], sz);
        }
#pragma unroll
        for (int i = 0; i < 4; i++) {
            int c = tid + i * 256;
            int br = c >> 3, bc = (c & 7) * 4;
            cpa16(sb + OFF_B + (uint32_t)(br * LDBF + bc) * 4,
                  &g_wt[(size_t)(n0 + br) * DHID + k0 + bc], 16);
        }
        CP_COMMIT();
    };

    issue_load(0, 0);
    issue_load(1, 1);

    const int NIT = DHID / BK;   // 32
    for (int kt = 0; kt < NIT; kt++) {
        if (kt + 2 < NIT) issue_load(kt + 2, (kt + 2) % STAGES);
        else CP_COMMIT();
        CP_WAIT2();
        __syncthreads();

        uint32_t sb = sbase + (kt % STAGES) * STG;

#pragma unroll
        for (int ks = 0; ks < 4; ks++) {
            uint32_t Af[4][4], Bf[4][2];
#pragma unroll
            for (int mt = 0; mt < 4; mt++) {
                uint32_t off = ((wm * 64 + mt * 16 + a_lr) * LDAF + ks * 8 + a_lc4) * 4;
                ldsm4(Af[mt], sb + off);
            }
#pragma unroll
            for (int p = 0; p < 2; p++) {
                uint32_t off = ((wn * 32 + p * 16 + b_lr) * LDBF + ks * 8 + b_lc4) * 4;
                uint32_t r[4];
                ldsm4(r, sb + OFF_B + off);
                Bf[p * 2][0] = r[0];     Bf[p * 2][1] = r[1];
                Bf[p * 2 + 1][0] = r[2]; Bf[p * 2 + 1][1] = r[3];
            }
#pragma unroll
            for (int mt = 0; mt < 4; mt++)
#pragma unroll
                for (int q = 0; q < 4; q++) Af[mt][q] = tf32r_u(Af[mt][q]);
#pragma unroll
            for (int mt = 0; mt < 4; mt++)
#pragma unroll
                for (int nt = 0; nt < 4; nt++)
                    mma_tf32(C[mt][nt], Af[mt], Bf[nt]);
        }
        __syncthreads();
    }

    // ---- epilogue: store h (fp16) + fused partial al/ar ----
    float av_l[8], av_r[8];
#pragma unroll
    for (int nt = 0; nt < 4; nt++) {
        int col = n0 + wn * 32 + nt * 8 + (lane & 3) * 2;
        av_l[nt * 2] = avec[col];        av_l[nt * 2 + 1] = avec[col + 1];
        av_r[nt * 2] = avec[DHID + col]; av_r[nt * 2 + 1] = avec[DHID + col + 1];
    }
#pragma unroll
    for (int mt = 0; mt < 4; mt++) {
        int row = m0 + wm * 64 + mt * 16 + (lane >> 2);
        float pl0 = 0.f, pr0 = 0.f, pl1 = 0.f, pr1 = 0.f;
#pragma unroll
        for (int nt = 0; nt < 4; nt++) {
            int col = n0 + wn * 32 + nt * 8 + (lane & 3) * 2;
            if (row < M) {
                *(__half2*)&g_hh[(size_t)row * DHID + col] =
                    __floats2half2_rn(C[mt][nt][0], C[mt][nt][1]);
            }
            if (row + 8 < M) {
                *(__half2*)&g_hh[(size_t)(row + 8) * DHID + col] =
                    __floats2half2_rn(C[mt][nt][2], C[mt][nt][3]);
            }
            pl0 += C[mt][nt][0] * av_l[nt * 2] + C[mt][nt][1] * av_l[nt * 2 + 1];
            pr0 += C[mt][nt][0] * av_r[nt * 2] + C[mt][nt][1] * av_r[nt * 2 + 1];
            pl1 += C[mt][nt][2] * av_l[nt * 2] + C[mt][nt][3] * av_l[nt * 2 + 1];
            pr1 += C[mt][nt][2] * av_r[nt * 2] + C[mt][nt][3] * av_r[nt * 2 + 1];
        }
#pragma unroll
        for (int o = 1; o < 4; o <<= 1) {
            pl0 += __shfl_xor_sync(0xffffffffu, pl0, o);
            pr0 += __shfl_xor_sync(0xffffffffu, pr0, o);
            pl1 += __shfl_xor_sync(0xffffffffu, pl1, o);
            pr1 += __shfl_xor_sync(0xffffffffu, pr1, o);
        }
        if ((lane & 3) == 0) {
            if (row < M)     { atomicAdd(&g_al[row], pl0);     atomicAdd(&g_ar[row], pr0); }
            if (row + 8 < M) { atomicAdd(&g_al[row + 8], pl1); atomicAdd(&g_ar[row + 8], pr1); }
        }
    }
}

// convert + fused src histogram
__global__ void convert_kernel(const void* __restrict__ src,
                               const void* __restrict__ dst, int E) {
    int k = blockIdx.x * blockDim.x + threadIdx.x;
    if (k >= E) return;
    int s, d;
    if (g_is64) {
        s = (int)((const long long*)src)[k];
        d = (int)((const long long*)dst)[k];
    } else {
        s = ((const int*)src)[k];
        d = ((const int*)dst)[k];
    }
    g_src[k] = s;
    g_dst[k] = d;
    atomicAdd(&g_counts[s], 1);
}

// ---------------- exclusive scan: 10 elems/thread + shfl block scan ------
__global__ void scan_kernel(int N) {
    __shared__ int warp_tot[32];
    int tid = threadIdx.x;
    int lane = tid & 31, wrp = tid >> 5;
    int base = tid * 10;
    int loc[10];
    int s = 0;
#pragma unroll
    for (int q = 0; q < 10; q++) {
        int idx = base + q;
        int val = (idx < N) ? g_counts[idx] : 0;
        loc[q] = s;
        s += val;
    }
    int inc = s;
#pragma unroll
    for (int o = 1; o < 32; o <<= 1) {
        int t = __shfl_up_sync(0xffffffffu, inc, o);
        if (lane >= o) inc += t;
    }
    if (lane == 31) warp_tot[wrp] = inc;
    __syncthreads();
    if (wrp == 0) {
        int w = warp_tot[lane];
#pragma unroll
        for (int o = 1; o < 32; o <<= 1) {
            int t = __shfl_up_sync(0xffffffffu, w, o);
            if (lane >= o) w += t;
        }
        warp_tot[lane] = w;
    }
    __syncthreads();
    int warp_off = (wrp > 0) ? warp_tot[wrp - 1] : 0;
    int thr_excl = warp_off + inc - s;
#pragma unroll
    for (int q = 0; q < 10; q++) {
        int idx = base + q;
        if (idx < N) g_offsets[idx] = thr_excl + loc[q];
    }
    if (tid == 1023) g_offsets[N] = thr_excl + s;
}

// ---------------- edge weights + scatter into src-sorted order ----------
__global__ void scatter_kernel(int E) {
    int k = blockIdx.x * blockDim.x + threadIdx.x;
    if (k >= E) return;
    int s = g_src[k];
    int d = g_dst[k];
    float z = g_al[s] + g_ar[d];
    z = (z > 0.f) ? z : NEG_SLOPE * z;          // leaky_relu
    float ee = expf(-z);
    int pos = g_offsets[s] + atomicAdd(&g_cursor[s], 1);
    g_e_sorted[pos] = ee;
    g_dst_sorted[pos] = d;
}

// ---------------- CSR SpMM (fp16 gather) + normalize + ELU --------------
// one block of 128 threads per row; each thread owns 8 columns (16B loads)
__global__ __launch_bounds__(128)
void spmm_kernel(float* __restrict__ out, int N) {
    int row = blockIdx.x;
    if (row >= N) return;
    int tid = threadIdx.x;
    int beg = g_offsets[row];
    int end = g_offsets[row + 1];

    __shared__ float se[128];
    __shared__ int   sd[128];

    float acc[8];
#pragma unroll
    for (int q = 0; q < 8; q++) acc[q] = 0.f;
    float rs = 0.f;
    int c = tid * 8;

    for (int base = beg; base < end; base += 128) {
        int nload = end - base;
        if (nload > 128) nload = 128;
        if (tid < nload) {
            se[tid] = g_e_sorted[base + tid];
            sd[tid] = g_dst_sorted[base + tid];
        }
        __syncthreads();
        for (int j = 0; j < nload; j++) {
            float ev = se[j];
            int d = sd[j];
            uint4 hv = *(const uint4*)&g_hh[(size_t)d * DHID + c];
            const __half2* hp = (const __half2*)&hv;
#pragma unroll
            for (int q = 0; q < 4; q++) {
                float2 f = __half22float2(hp[q]);
                acc[q * 2]     += ev * f.x;
                acc[q * 2 + 1] += ev * f.y;
            }
            rs += ev;
        }
        __syncthreads();
    }

    float inv = 1.f / (rs + EPS_V);
    float4 o0, o1;
    float v;
    v = acc[0] * inv; o0.x = (v > 0.f) ? v : expm1f(v);
    v = acc[1] * inv; o0.y = (v > 0.f) ? v : expm1f(v);
    v = acc[2] * inv; o0.z = (v > 0.f) ? v : expm1f(v);
    v = acc[3] * inv; o0.w = (v > 0.f) ? v : expm1f(v);
    v = acc[4] * inv; o1.x = (v > 0.f) ? v : expm1f(v);
    v = acc[5] * inv; o1.y = (v > 0.f) ? v : expm1f(v);
    v = acc[6] * inv; o1.z = (v > 0.f) ? v : expm1f(v);
    v = acc[7] * inv; o1.w = (v > 0.f) ? v : expm1f(v);
    *(float4*)&out[(size_t)row * DHID + c] = o0;
    *(float4*)&out[(size_t)row * DHID + c + 4] = o1;
}

// ---------------- launch ----------------
extern "C" void kernel_launch(void* const* d_in, const int* in_sizes, int n_in,
                              void* d_out, int out_size) {
    const float* x = (const float*)d_in[0];
    const float* W = (const float*)d_in[1];
    const float* a = (const float*)d_in[2];
    const void* src = d_in[3];
    const void* dst = d_in[4];
    float* out = (float*)d_out;

    int N = in_sizes[0] / DHID;   // 10000
    int E = in_sizes[3];          // 160000
    if (N > MAXN) N = MAXN;
    if (E > MAXE) E = MAXE;

    static cudaStream_t s2 = 0;
    static cudaEvent_t ev_fork = 0, ev_join = 0;
    if (!s2) {
        cudaStreamCreateWithFlags(&s2, cudaStreamNonBlocking);
        cudaEventCreateWithFlags(&ev_fork, cudaEventDisableTiming);
        cudaEventCreateWithFlags(&ev_join, cudaEventDisableTiming);
        cudaFuncSetAttribute(gemm_mma_kernel,
                             cudaFuncAttributeMaxDynamicSharedMemorySize, GEMM_SMEM);
    }

    init_detect_kernel<<<(N + 255) / 256, 256>>>(src, E, N);

    // fork: edge prelude runs concurrently with W-prep + GEMM
    cudaEventRecord(ev_fork, 0);
    cudaStreamWaitEvent(s2, ev_fork, 0);

    wt_round_kernel<<<dim3(DHID / 32, DHID / 32), dim3(32, 8)>>>(W);
    dim3 ggrid(DHID / BN, (N + BM - 1) / BM);
    gemm_mma_kernel<<<ggrid, 256, GEMM_SMEM>>>(x, a, N);

    convert_kernel<<<(E + 255) / 256, 256, 0, s2>>>(src, dst, E);
    scan_kernel<<<1, 1024, 0, s2>>>(N);
    cudaEventRecord(ev_join, s2);

    cudaStreamWaitEvent(0, ev_join, 0);
    scatter_kernel<<<(E + 255) / 256, 256>>>(E);
    spmm_kernel<<<N, 128>>>(out, N);
}